// round 7
// baseline (speedup 1.0000x reference)
#include <cuda_runtime.h>
#include <cuda_bf16.h>
#include <cstdint>

#define B_ 64
#define T_ 1024
#define I_ 256
#define H_ 512
#define O_ 256
#define G_ 1536   // 3*H

struct __align__(16) ull2 { unsigned long long x, y; };

#define FMA2(acc, av, bv) \
    asm("fma.rn.f32x2 %0, %1, %2, %0;" : "+l"(acc) : "l"(av), "l"(bv))

// ======================= scratch (device globals) =======================
__device__ float g_gates[(size_t)T_ * G_ * B_];   // [t][g][b]
__device__ float g_out0[(size_t)T_ * H_ * B_];    // [t][h][b]
__device__ float g_out1[(size_t)T_ * H_ * B_];    // [t][h][b]

// pre-swizzled bf16 operand tiles
__device__ __nv_bfloat16 g_w0h[12 * 4 * 8192], g_w0l[12 * 4 * 8192];
__device__ __nv_bfloat16 g_w1h[12 * 8 * 8192], g_w1l[12 * 8 * 8192];
__device__ __nv_bfloat16 g_wfh[ 2 * 8 * 8192], g_wfl[ 2 * 8 * 8192];
__device__ __nv_bfloat16 g_x0h[(size_t)T_ * 4 * 4096], g_x0l[(size_t)T_ * 4 * 4096];
__device__ __nv_bfloat16 g_x1h[(size_t)T_ * 8 * 4096], g_x1l[(size_t)T_ * 8 * 4096];

// ======================= small helpers =======================
__device__ __forceinline__ void cp_async16(void* smem_dst, const void* gsrc) {
    unsigned s = (unsigned)__cvta_generic_to_shared(smem_dst);
    asm volatile("cp.async.ca.shared.global [%0], [%1], 16;" :: "r"(s), "l"(gsrc));
}
__device__ __forceinline__ void cp_commit() {
    asm volatile("cp.async.commit_group;");
}
template <int N>
__device__ __forceinline__ void cp_wait() {
    asm volatile("cp.async.wait_group %0;" :: "n"(N));
}
__device__ __forceinline__ float sum2(unsigned long long v) {
    unsigned lo, hi;
    asm("mov.b64 {%0, %1}, %2;" : "=r"(lo), "=r"(hi) : "l"(v));
    return __uint_as_float(lo) + __uint_as_float(hi);
}
__device__ __forceinline__ uint32_t smem_u32(const void* p) {
    return (uint32_t)__cvta_generic_to_shared(p);
}
__host__ __device__ __forceinline__ uint32_t swz128(uint32_t o) {
    return o ^ ((o >> 3) & 0x70);
}
__device__ __forceinline__ unsigned short bf16hi_bits(float v, float& rem) {
    __nv_bfloat16 b = __float2bfloat16(v);
    rem = v - __bfloat162float(b);
    return *reinterpret_cast<unsigned short*>(&b);
}
__device__ __forceinline__ unsigned short bf16_bits(float v) {
    __nv_bfloat16 b = __float2bfloat16(v);
    return *reinterpret_cast<unsigned short*>(&b);
}

// ---- mma.sync / ldmatrix (base-target PTX) ----
__device__ __forceinline__ void ldsm_x4(unsigned* r, uint32_t addr) {
    asm volatile("ldmatrix.sync.aligned.m8n8.x4.shared.b16 {%0,%1,%2,%3}, [%4];"
        : "=r"(r[0]), "=r"(r[1]), "=r"(r[2]), "=r"(r[3]) : "r"(addr));
}
__device__ __forceinline__ void mma_bf16(float* d, const unsigned* a, const unsigned* b) {
    asm volatile(
        "mma.sync.aligned.m16n8k16.row.col.f32.bf16.bf16.f32 "
        "{%0,%1,%2,%3}, {%4,%5,%6,%7}, {%8,%9}, {%0,%1,%2,%3};"
        : "+f"(d[0]), "+f"(d[1]), "+f"(d[2]), "+f"(d[3])
        : "r"(a[0]), "r"(a[1]), "r"(a[2]), "r"(a[3]), "r"(b[0]), "r"(b[1]));
}

// =========================================================================
// Prep: W [M,K] fp32 -> hi/lo bf16 SW128 tiles [mi][s][128x64]
// =========================================================================
__global__ __launch_bounds__(256) void k_prep_w(
    const float* __restrict__ src, __nv_bfloat16* __restrict__ dh,
    __nv_bfloat16* __restrict__ dl, int K)
{
    int mi = blockIdx.x, s = blockIdx.y, nS = gridDim.y;
    size_t tbase = ((size_t)mi * nS + s) * 16384;
#pragma unroll
    for (int i = 0; i < 8; i++) {
        int it  = threadIdx.x + i * 256;
        int row = it >> 4;
        int q   = it & 15;
        float4 v = *(const float4*)(src + (size_t)(mi * 128 + row) * K + s * 64 + q * 4);
        float r0, r1, r2, r3;
        ushort4 hi, lo;
        hi.x = bf16hi_bits(v.x, r0); hi.y = bf16hi_bits(v.y, r1);
        hi.z = bf16hi_bits(v.z, r2); hi.w = bf16hi_bits(v.w, r3);
        lo.x = bf16_bits(r0); lo.y = bf16_bits(r1);
        lo.z = bf16_bits(r2); lo.w = bf16_bits(r3);
        uint32_t sw = swz128((uint32_t)(row * 128 + q * 8));
        *(ushort4*)((char*)dh + tbase + sw) = hi;
        *(ushort4*)((char*)dl + tbase + sw) = lo;
    }
}

// =========================================================================
// Prep: x[b][t][k] fp32 -> hi/lo bf16 SW128 tiles [t][s][64(b)x64(k)]
// =========================================================================
__global__ __launch_bounds__(256) void k_prep_x(const float* __restrict__ x) {
    int t = blockIdx.x, s = blockIdx.y, nS = gridDim.y;
    size_t tbase = ((size_t)t * nS + s) * 8192;
#pragma unroll
    for (int i = 0; i < 4; i++) {
        int it = threadIdx.x + i * 256;
        int b  = it >> 4;
        int q  = it & 15;
        float4 v = *(const float4*)(x + ((size_t)b * T_ + t) * I_ + s * 64 + q * 4);
        float r0, r1, r2, r3;
        ushort4 hi, lo;
        hi.x = bf16hi_bits(v.x, r0); hi.y = bf16hi_bits(v.y, r1);
        hi.z = bf16hi_bits(v.z, r2); hi.w = bf16hi_bits(v.w, r3);
        lo.x = bf16_bits(r0); lo.y = bf16_bits(r1);
        lo.z = bf16_bits(r2); lo.w = bf16_bits(r3);
        uint32_t sw = swz128((uint32_t)(b * 128 + q * 8));
        *(ushort4*)((char*)g_x0h + tbase + sw) = hi;
        *(ushort4*)((char*)g_x0l + tbase + sw) = lo;
    }
}

// =========================================================================
// Prep: out[t][h][b] fp32 -> hi/lo bf16 SW128 tiles [t][s][64(b)x64(k)]
// =========================================================================
__global__ __launch_bounds__(256) void k_prep_h(
    const float* __restrict__ src, __nv_bfloat16* __restrict__ dh,
    __nv_bfloat16* __restrict__ dl)
{
    __shared__ float sm[64 * 65];
    int t = blockIdx.x, s = blockIdx.y, nS = gridDim.y;
    size_t tbase = ((size_t)t * nS + s) * 8192;
    const float* blk = src + ((size_t)t * H_ + s * 64) * B_;
#pragma unroll
    for (int i = 0; i < 16; i++) {
        int idx = threadIdx.x + i * 256;
        int k = idx >> 6, b = idx & 63;
        sm[k * 65 + b] = blk[idx];
    }
    __syncthreads();
#pragma unroll
    for (int i = 0; i < 4; i++) {
        int it = threadIdx.x + i * 256;
        int b  = it >> 4;
        int q  = it & 15;
        float v0 = sm[(q * 4 + 0) * 65 + b];
        float v1 = sm[(q * 4 + 1) * 65 + b];
        float v2 = sm[(q * 4 + 2) * 65 + b];
        float v3 = sm[(q * 4 + 3) * 65 + b];
        float r0, r1, r2, r3;
        ushort4 hi, lo;
        hi.x = bf16hi_bits(v0, r0); hi.y = bf16hi_bits(v1, r1);
        hi.z = bf16hi_bits(v2, r2); hi.w = bf16hi_bits(v3, r3);
        lo.x = bf16_bits(r0); lo.y = bf16_bits(r1);
        lo.z = bf16_bits(r2); lo.w = bf16_bits(r3);
        uint32_t sw = swz128((uint32_t)(b * 128 + q * 8));
        *(ushort4*)((char*)dh + tbase + sw) = hi;
        *(ushort4*)((char*)dl + tbase + sw) = lo;
    }
}

// =========================================================================
// mma.sync GEMM (unchanged from R6)
// =========================================================================
#define TCB_BYTES 65536
#define TC_SMEM_TOTAL (1024 + 2 * TCB_BYTES)

__global__ __launch_bounds__(256) void k_gemm_mma(
    const __nv_bfloat16* __restrict__ Wh, const __nv_bfloat16* __restrict__ Wl,
    const __nv_bfloat16* __restrict__ Xh, const __nv_bfloat16* __restrict__ Xl,
    const float* __restrict__ bias, float* __restrict__ C,
    int nS, int M, int mode)
{
    extern __shared__ __align__(16) char smem[];
    uint32_t sb = smem_u32(smem);
    int tid  = threadIdx.x;
    int wid  = tid >> 5;
    int lane = tid & 31;
    int mi   = blockIdx.x;
    int m0   = mi * 128;
    int t0   = blockIdx.y * 2;

    int wm = (wid >> 1) * 32;
    int wn = (wid & 1);

    uint32_t pA = (uint32_t)((wm + (lane & 15)) * 128 + (lane >> 4) * 16);
    uint32_t rowB = (uint32_t)((lane & 7) + ((lane >> 4) & 1) * 8);
    uint32_t koffB = (uint32_t)(((lane >> 3) & 1) * 16);

    float acc[2][8][4];
#pragma unroll
    for (int i = 0; i < 2; i++)
#pragma unroll
        for (int n = 0; n < 8; n++)
#pragma unroll
            for (int c = 0; c < 4; c++) acc[i][n][c] = 0.f;

    auto issue_slab = [&](int s, int bi) {
        char* dst = smem + 1024 + bi * TCB_BYTES;
        const char* wh  = (const char*)Wh + ((size_t)mi * nS + s) * 16384;
        const char* wl  = (const char*)Wl + ((size_t)mi * nS + s) * 16384;
        const char* x0h = (const char*)Xh + ((size_t)t0 * nS + s) * 8192;
        const char* x1h = (const char*)Xh + ((size_t)(t0 + 1) * nS + s) * 8192;
        const char* x0l = (const char*)Xl + ((size_t)t0 * nS + s) * 8192;
        const char* x1l = (const char*)Xl + ((size_t)(t0 + 1) * nS + s) * 8192;
#pragma unroll
        for (int i = 0; i < 16; i++) {
            int c   = tid + i * 256;
            int reg = c >> 10;
            int off = (c & 1023) * 16;
            const char* src;
            if      (reg == 0) src = wh + off;
            else if (reg == 1) src = wl + off;
            else if (reg == 2) src = (off < 8192) ? x0h + off : x1h + (off - 8192);
            else               src = (off < 8192) ? x0l + off : x1l + (off - 8192);
            cp_async16(dst + reg * 16384 + off, src);
        }
        cp_commit();
    };

    issue_slab(0, 0);

    for (int s = 0; s < nS; s++) {
        int bi = s & 1;
        if (s + 1 < nS) {
            issue_slab(s + 1, (s + 1) & 1);
            cp_wait<1>();
        } else {
            cp_wait<0>();
        }
        __syncthreads();

        uint32_t bufb = sb + 1024 + (uint32_t)bi * TCB_BYTES;
        uint32_t aH = bufb;
        uint32_t aL = bufb + 16384;
        uint32_t bH = bufb + 32768 + (uint32_t)wn * 8192;
        uint32_t bL = bufb + 49152 + (uint32_t)wn * 8192;

#pragma unroll
        for (int ks = 0; ks < 4; ks++) {
            unsigned ah[2][4], al[2][4];
            ldsm_x4(ah[0], aH + swz128(pA + ks * 32));
            ldsm_x4(ah[1], aH + swz128(pA + 2048 + ks * 32));
            ldsm_x4(al[0], aL + swz128(pA + ks * 32));
            ldsm_x4(al[1], aL + swz128(pA + 2048 + ks * 32));
#pragma unroll
            for (int half = 0; half < 2; half++) {
                unsigned bh2[2][4], bl2[2][4];
#pragma unroll
                for (int np2 = 0; np2 < 2; np2++) {
                    int np = half * 2 + np2;
                    uint32_t pB = (uint32_t)((np * 16 + rowB) * 128) + koffB;
                    ldsm_x4(bh2[np2], bH + swz128(pB + ks * 32));
                    ldsm_x4(bl2[np2], bL + swz128(pB + ks * 32));
                }
#pragma unroll
                for (int np2 = 0; np2 < 2; np2++) {
#pragma unroll
                    for (int e = 0; e < 2; e++) {
                        int nt = half * 4 + np2 * 2 + e;
                        const unsigned* bfh = &bh2[np2][e * 2];
                        const unsigned* bfl = &bl2[np2][e * 2];
#pragma unroll
                        for (int i = 0; i < 2; i++) {
                            mma_bf16(acc[i][nt], ah[i], bfh);
                            mma_bf16(acc[i][nt], ah[i], bfl);
                            mma_bf16(acc[i][nt], al[i], bfh);
                        }
                    }
                }
            }
        }
        __syncthreads();
    }

    int qrow = lane >> 2;
    int qcol = (lane & 3) * 2;

    if (mode == 0) {
        int t = t0 + wn;
#pragma unroll
        for (int i = 0; i < 2; i++) {
            int r0 = wm + i * 16 + qrow;
            int r1 = r0 + 8;
            float bb0 = bias[m0 + r0];
            float bb1 = bias[m0 + r1];
            float* d0 = C + ((size_t)t * M + m0 + r0) * B_;
            float* d1 = C + ((size_t)t * M + m0 + r1) * B_;
#pragma unroll
            for (int nt = 0; nt < 8; nt++) {
                int col = nt * 8 + qcol;
                *(float2*)(d0 + col) = make_float2(acc[i][nt][0] + bb0, acc[i][nt][1] + bb0);
                *(float2*)(d1 + col) = make_float2(acc[i][nt][2] + bb1, acc[i][nt][3] + bb1);
            }
        }
    } else {
        float* stage = (float*)(smem + 1024);
#pragma unroll
        for (int i = 0; i < 2; i++) {
            int r0 = wm + i * 16 + qrow;
            int r1 = r0 + 8;
            float bb0 = bias[m0 + r0];
            float bb1 = bias[m0 + r1];
#pragma unroll
            for (int nt = 0; nt < 8; nt++) {
                int col = wn * 64 + nt * 8 + qcol;
                stage[r0 * 132 + col]     = acc[i][nt][0] + bb0;
                stage[r0 * 132 + col + 1] = acc[i][nt][1] + bb0;
                stage[r1 * 132 + col]     = acc[i][nt][2] + bb1;
                stage[r1 * 132 + col + 1] = acc[i][nt][3] + bb1;
            }
        }
        __syncthreads();
        int n    = tid >> 1;
        int half = tid & 1;
        int tt   = t0 + (n >> 6);
        int b2   = n & 63;
        float* dst = C + ((size_t)b2 * T_ + tt) * M + m0 + half * 64;
#pragma unroll
        for (int q = 0; q < 16; q++) {
            float4 v = make_float4(stage[(half * 64 + q * 4 + 0) * 132 + n],
                                   stage[(half * 64 + q * 4 + 1) * 132 + n],
                                   stage[(half * 64 + q * 4 + 2) * 132 + n],
                                   stage[(half * 64 + q * 4 + 3) * 132 + n]);
            *(float4*)(dst + q * 4) = v;
        }
    }
}

// =========================================================================
// Persistent GRU layer, CLUSTER version.
// 128 CTAs = 8 clusters of 16. Cluster = one batch-group (8 b).
// CTA rank owns 32 j (x3 gates): W slice 96x512 fp32 in SMEM (~195KB),
// h slice [8 b][512 k] (~16KB). Sync = barrier.cluster (release/acquire).
// =========================================================================
#define WS5_ROWS 96
#define WS5_STRIDE 520
#define HS5_STRIDE 516
#define GRU5_SMEM_BYTES ((WS5_ROWS * WS5_STRIDE + 8 * HS5_STRIDE) * 4)

__global__ __launch_bounds__(256) __cluster_dims__(16, 1, 1)
void k_gru5(
    const float* __restrict__ gates,   // [t][g][b], includes b_ih
    const float* __restrict__ Whh,     // [3H][H]
    const float* __restrict__ bhh,     // [3H]
    float* __restrict__ out)           // [t][h][b]
{
    extern __shared__ float smemf[];
    float* Ws = smemf;                          // 96 rows (j*3+g) x WS5_STRIDE
    float* hs = smemf + WS5_ROWS * WS5_STRIDE;  // [8 b][HS5_STRIDE]

    int tid   = threadIdx.x;
    int group = blockIdx.x >> 4;    // 0..7 (batch group of 8)
    int rank  = blockIdx.x & 15;    // 0..15 (j partition of 32)
    int j     = tid >> 3;           // 0..31
    int bl    = tid & 7;            // 0..7
    int j0    = rank * 32;
    int bg0   = group * 8;
    int jg    = j0 + j;
    int bg    = bg0 + bl;

    // Load Whh slice: row (w*3+g) <- Whh[g*H + j0 + w]
    for (int idx = tid; idx < WS5_ROWS * 512; idx += 256) {
        int r = idx >> 9;           // 0..95
        int k = idx & 511;
        int gg = r % 3;
        int ww = r / 3;
        Ws[r * WS5_STRIDE + k] = Whh[((size_t)(gg * H_ + j0 + ww)) * H_ + k];
    }
    for (int idx = tid; idx < 8 * HS5_STRIDE; idx += 256) hs[idx] = 0.f;

    float bhr = bhh[jg];
    float bhz = bhh[H_ + jg];
    float bhn = bhh[2 * H_ + jg];

    const ull2* Wr2 = (const ull2*)(Ws + (j * 3 + 0) * WS5_STRIDE);
    const ull2* Wz2 = (const ull2*)(Ws + (j * 3 + 1) * WS5_STRIDE);
    const ull2* Wn2 = (const ull2*)(Ws + (j * 3 + 2) * WS5_STRIDE);
    const ull2* hrow = (const ull2*)(hs + bl * HS5_STRIDE);

    const float* gp = gates + (size_t)jg * B_ + bg;
    const size_t tstride = (size_t)G_ * B_;
    const size_t goff    = (size_t)H_ * B_;

    float xr = __ldcs(gp);
    float xz = __ldcs(gp + goff);
    float xn = __ldcs(gp + 2 * goff);

    __syncthreads();

    for (int t = 0; t < T_; t++) {
        unsigned long long ar2 = 0ull, az2 = 0ull, an2 = 0ull;
#pragma unroll 8
        for (int i = 0; i < 128; i++) {
            ull2 h2 = hrow[i];
            ull2 wr = Wr2[i];
            ull2 wz = Wz2[i];
            ull2 wn = Wn2[i];
            FMA2(ar2, wr.x, h2.x); FMA2(ar2, wr.y, h2.y);
            FMA2(az2, wz.x, h2.x); FMA2(az2, wz.y, h2.y);
            FMA2(an2, wn.x, h2.x); FMA2(an2, wn.y, h2.y);
        }
        float ar = sum2(ar2);
        float az = sum2(az2);
        float an = sum2(an2);

        float r = 1.f / (1.f + expf(-(xr + ar + bhr)));
        float z = 1.f / (1.f + expf(-(xz + az + bhz)));
        float n = tanhf(xn + r * (an + bhn));
        float hold = hs[bl * HS5_STRIDE + jg];
        float hnew = (1.f - z) * n + z * hold;

        out[((size_t)t * H_ + jg) * B_ + bg] = hnew;

        // prefetch next-step gates (independent of h)
        if (t + 1 < T_) {
            const float* gq = gp + (size_t)(t + 1) * tstride;
            xr = __ldcs(gq);
            xz = __ldcs(gq + goff);
            xn = __ldcs(gq + 2 * goff);
        }

        // ---- cluster barrier: release h(t) writes, acquire peers' ----
        asm volatile("barrier.cluster.arrive.aligned;" ::: "memory");
        asm volatile("barrier.cluster.wait.aligned;" ::: "memory");

        // ---- reload group's h slice: hs[b_local][k] <- out[t][k][bg0+b] ----
        {
            const float* src = out + (size_t)t * H_ * B_;
#pragma unroll
            for (int u = 0; u < 4; u++) {
                int idx = tid + u * 256;          // 0..1023
                int k = idx >> 1;                  // 0..511
                int q = idx & 1;                   // which float4 (4 b)
                float4 v = __ldcg(reinterpret_cast<const float4*>(src + (size_t)k * B_ + bg0) + q);
                int bb = q * 4;
                hs[(bb + 0) * HS5_STRIDE + k] = v.x;
                hs[(bb + 1) * HS5_STRIDE + k] = v.y;
                hs[(bb + 2) * HS5_STRIDE + k] = v.z;
                hs[(bb + 3) * HS5_STRIDE + k] = v.w;
            }
        }
        __syncthreads();
    }
}

// =========================================================================
// hidden[l][b][h] = out_l[T-1][h][b]
// =========================================================================
__global__ __launch_bounds__(256) void k_hidden(float* __restrict__ dst) {
    int idx = blockIdx.x * 256 + threadIdx.x;
    int l  = idx >> 15;
    int rem = idx & 32767;
    int bb = rem >> 9;
    int h  = rem & 511;
    const float* src = l ? g_out1 : g_out0;
    dst[idx] = src[((size_t)(T_ - 1) * H_ + h) * B_ + bb];
}

// =========================================================================
extern "C" void kernel_launch(void* const* d_in, const int* in_sizes, int n_in,
                              void* d_out, int out_size) {
    const float* x    = (const float*)d_in[0];
    const float* Wih0 = (const float*)d_in[1];
    const float* Whh0 = (const float*)d_in[2];
    const float* bih0 = (const float*)d_in[3];
    const float* bhh0 = (const float*)d_in[4];
    const float* Wih1 = (const float*)d_in[5];
    const float* Whh1 = (const float*)d_in[6];
    const float* bih1 = (const float*)d_in[7];
    const float* bhh1 = (const float*)d_in[8];
    const float* fcw  = (const float*)d_in[9];
    const float* fcb  = (const float*)d_in[10];
    float* out = (float*)d_out;

    (void)in_sizes; (void)n_in; (void)out_size;

    cudaFuncSetAttribute(k_gru5, cudaFuncAttributeMaxDynamicSharedMemorySize,
                         GRU5_SMEM_BYTES);
    cudaFuncSetAttribute(k_gru5, cudaFuncAttributeNonPortableClusterSizeAllowed, 1);
    cudaFuncSetAttribute(k_gemm_mma, cudaFuncAttributeMaxDynamicSharedMemorySize,
                         TC_SMEM_TOTAL);

    float *p_gates, *p_out0, *p_out1;
    cudaGetSymbolAddress((void**)&p_gates, g_gates);
    cudaGetSymbolAddress((void**)&p_out0,  g_out0);
    cudaGetSymbolAddress((void**)&p_out1,  g_out1);
    __nv_bfloat16 *w0h, *w0l, *w1h, *w1l, *wfh, *wfl, *x0h, *x0l, *x1h, *x1l;
    cudaGetSymbolAddress((void**)&w0h, g_w0h);
    cudaGetSymbolAddress((void**)&w0l, g_w0l);
    cudaGetSymbolAddress((void**)&w1h, g_w1h);
    cudaGetSymbolAddress((void**)&w1l, g_w1l);
    cudaGetSymbolAddress((void**)&wfh, g_wfh);
    cudaGetSymbolAddress((void**)&wfl, g_wfl);
    cudaGetSymbolAddress((void**)&x0h, g_x0h);
    cudaGetSymbolAddress((void**)&x0l, g_x0l);
    cudaGetSymbolAddress((void**)&x1h, g_x1h);
    cudaGetSymbolAddress((void**)&x1l, g_x1l);

    // operand prep
    k_prep_w<<<dim3(12, 4), 256>>>(Wih0, w0h, w0l, I_);
    k_prep_w<<<dim3(12, 8), 256>>>(Wih1, w1h, w1l, H_);
    k_prep_w<<<dim3(2, 8),  256>>>(fcw,  wfh, wfl, H_);
    k_prep_x<<<dim3(1024, 4), 256>>>(x);

    // layer 0
    k_gemm_mma<<<dim3(12, 512), 256, TC_SMEM_TOTAL>>>(w0h, w0l, x0h, x0l, bih0, p_gates, 4, G_, 0);
    k_gru5<<<128, 256, GRU5_SMEM_BYTES>>>(p_gates, Whh0, bhh0, p_out0);

    // layer 1
    k_prep_h<<<dim3(1024, 8), 256>>>(p_out0, x1h, x1l);
    k_gemm_mma<<<dim3(12, 512), 256, TC_SMEM_TOTAL>>>(w1h, w1l, x1h, x1l, bih1, p_gates, 8, G_, 0);
    k_gru5<<<128, 256, GRU5_SMEM_BYTES>>>(p_gates, Whh1, bhh1, p_out1);

    // FC
    k_prep_h<<<dim3(1024, 8), 256>>>(p_out1, x1h, x1l);
    k_gemm_mma<<<dim3(2, 512), 256, TC_SMEM_TOTAL>>>(wfh, wfl, x1h, x1l, fcb, out, 8, O_, 1);

    k_hidden<<<256, 256>>>(out + (size_t)B_ * T_ * O_);
}

// round 8
// speedup vs baseline: 1.0398x; 1.0398x over previous
#include <cuda_runtime.h>
#include <cuda_bf16.h>
#include <cstdint>

#define B_ 64
#define T_ 1024
#define I_ 256
#define H_ 512
#define O_ 256
#define G_ 1536   // 3*H

struct __align__(16) ull2 { unsigned long long x, y; };

#define FMA2(acc, av, bv) \
    asm("fma.rn.f32x2 %0, %1, %2, %0;" : "+l"(acc) : "l"(av), "l"(bv))

// ======================= scratch (device globals) =======================
__device__ float g_gates[(size_t)T_ * G_ * B_];   // [t][g][b]
__device__ float g_out0[(size_t)T_ * H_ * B_];    // [t][h][b]
__device__ float g_out1[(size_t)T_ * H_ * B_];    // [t][h][b]
__device__ unsigned g_flags[4 * 32];               // per-(group,cta) epoch flags

// pre-swizzled bf16 operand tiles
__device__ __nv_bfloat16 g_w0h[12 * 4 * 8192], g_w0l[12 * 4 * 8192];
__device__ __nv_bfloat16 g_w1h[12 * 8 * 8192], g_w1l[12 * 8 * 8192];
__device__ __nv_bfloat16 g_wfh[ 2 * 8 * 8192], g_wfl[ 2 * 8 * 8192];
__device__ __nv_bfloat16 g_x0h[(size_t)T_ * 4 * 4096], g_x0l[(size_t)T_ * 4 * 4096];
__device__ __nv_bfloat16 g_x1h[(size_t)T_ * 8 * 4096], g_x1l[(size_t)T_ * 8 * 4096];

// ======================= small helpers =======================
__device__ __forceinline__ void cp_async16(void* smem_dst, const void* gsrc) {
    unsigned s = (unsigned)__cvta_generic_to_shared(smem_dst);
    asm volatile("cp.async.ca.shared.global [%0], [%1], 16;" :: "r"(s), "l"(gsrc));
}
__device__ __forceinline__ void cp_commit() {
    asm volatile("cp.async.commit_group;");
}
template <int N>
__device__ __forceinline__ void cp_wait() {
    asm volatile("cp.async.wait_group %0;" :: "n"(N));
}
__device__ __forceinline__ unsigned ld_acquire(const unsigned* p) {
    unsigned v;
    asm volatile("ld.acquire.gpu.global.u32 %0, [%1];" : "=r"(v) : "l"(p) : "memory");
    return v;
}
__device__ __forceinline__ void st_release(unsigned* p, unsigned v) {
    asm volatile("st.release.gpu.global.u32 [%0], %1;" :: "l"(p), "r"(v) : "memory");
}
__device__ __forceinline__ float sum2(unsigned long long v) {
    unsigned lo, hi;
    asm("mov.b64 {%0, %1}, %2;" : "=r"(lo), "=r"(hi) : "l"(v));
    return __uint_as_float(lo) + __uint_as_float(hi);
}
__device__ __forceinline__ uint32_t smem_u32(const void* p) {
    return (uint32_t)__cvta_generic_to_shared(p);
}
__host__ __device__ __forceinline__ uint32_t swz128(uint32_t o) {
    return o ^ ((o >> 3) & 0x70);
}
__device__ __forceinline__ unsigned short bf16hi_bits(float v, float& rem) {
    __nv_bfloat16 b = __float2bfloat16(v);
    rem = v - __bfloat162float(b);
    return *reinterpret_cast<unsigned short*>(&b);
}
__device__ __forceinline__ unsigned short bf16_bits(float v) {
    __nv_bfloat16 b = __float2bfloat16(v);
    return *reinterpret_cast<unsigned short*>(&b);
}

// ---- mma.sync / ldmatrix (base-target PTX) ----
__device__ __forceinline__ void ldsm_x4(unsigned* r, uint32_t addr) {
    asm volatile("ldmatrix.sync.aligned.m8n8.x4.shared.b16 {%0,%1,%2,%3}, [%4];"
        : "=r"(r[0]), "=r"(r[1]), "=r"(r[2]), "=r"(r[3]) : "r"(addr));
}
__device__ __forceinline__ void mma_bf16(float* d, const unsigned* a, const unsigned* b) {
    asm volatile(
        "mma.sync.aligned.m16n8k16.row.col.f32.bf16.bf16.f32 "
        "{%0,%1,%2,%3}, {%4,%5,%6,%7}, {%8,%9}, {%0,%1,%2,%3};"
        : "+f"(d[0]), "+f"(d[1]), "+f"(d[2]), "+f"(d[3])
        : "r"(a[0]), "r"(a[1]), "r"(a[2]), "r"(a[3]), "r"(b[0]), "r"(b[1]));
}

// =========================================================================
// Zero the barrier flags (runs before each recurrent launch)
// =========================================================================
__global__ void k_zeroflags() {
    if (threadIdx.x < 4 * 32) g_flags[threadIdx.x] = 0u;
}

// =========================================================================
// Prep: W [M,K] fp32 -> hi/lo bf16 SW128 tiles [mi][s][128x64]
// =========================================================================
__global__ __launch_bounds__(256) void k_prep_w(
    const float* __restrict__ src, __nv_bfloat16* __restrict__ dh,
    __nv_bfloat16* __restrict__ dl, int K)
{
    int mi = blockIdx.x, s = blockIdx.y, nS = gridDim.y;
    size_t tbase = ((size_t)mi * nS + s) * 16384;
#pragma unroll
    for (int i = 0; i < 8; i++) {
        int it  = threadIdx.x + i * 256;
        int row = it >> 4;
        int q   = it & 15;
        float4 v = *(const float4*)(src + (size_t)(mi * 128 + row) * K + s * 64 + q * 4);
        float r0, r1, r2, r3;
        ushort4 hi, lo;
        hi.x = bf16hi_bits(v.x, r0); hi.y = bf16hi_bits(v.y, r1);
        hi.z = bf16hi_bits(v.z, r2); hi.w = bf16hi_bits(v.w, r3);
        lo.x = bf16_bits(r0); lo.y = bf16_bits(r1);
        lo.z = bf16_bits(r2); lo.w = bf16_bits(r3);
        uint32_t sw = swz128((uint32_t)(row * 128 + q * 8));
        *(ushort4*)((char*)dh + tbase + sw) = hi;
        *(ushort4*)((char*)dl + tbase + sw) = lo;
    }
}

// =========================================================================
// Prep: x[b][t][k] fp32 -> hi/lo bf16 SW128 tiles [t][s][64(b)x64(k)]
// =========================================================================
__global__ __launch_bounds__(256) void k_prep_x(const float* __restrict__ x) {
    int t = blockIdx.x, s = blockIdx.y, nS = gridDim.y;
    size_t tbase = ((size_t)t * nS + s) * 8192;
#pragma unroll
    for (int i = 0; i < 4; i++) {
        int it = threadIdx.x + i * 256;
        int b  = it >> 4;
        int q  = it & 15;
        float4 v = *(const float4*)(x + ((size_t)b * T_ + t) * I_ + s * 64 + q * 4);
        float r0, r1, r2, r3;
        ushort4 hi, lo;
        hi.x = bf16hi_bits(v.x, r0); hi.y = bf16hi_bits(v.y, r1);
        hi.z = bf16hi_bits(v.z, r2); hi.w = bf16hi_bits(v.w, r3);
        lo.x = bf16_bits(r0); lo.y = bf16_bits(r1);
        lo.z = bf16_bits(r2); lo.w = bf16_bits(r3);
        uint32_t sw = swz128((uint32_t)(b * 128 + q * 8));
        *(ushort4*)((char*)g_x0h + tbase + sw) = hi;
        *(ushort4*)((char*)g_x0l + tbase + sw) = lo;
    }
}

// =========================================================================
// Prep: out[t][h][b] fp32 -> hi/lo bf16 SW128 tiles [t][s][64(b)x64(k)]
// =========================================================================
__global__ __launch_bounds__(256) void k_prep_h(
    const float* __restrict__ src, __nv_bfloat16* __restrict__ dh,
    __nv_bfloat16* __restrict__ dl)
{
    __shared__ float sm[64 * 65];
    int t = blockIdx.x, s = blockIdx.y, nS = gridDim.y;
    size_t tbase = ((size_t)t * nS + s) * 8192;
    const float* blk = src + ((size_t)t * H_ + s * 64) * B_;
#pragma unroll
    for (int i = 0; i < 16; i++) {
        int idx = threadIdx.x + i * 256;
        int k = idx >> 6, b = idx & 63;
        sm[k * 65 + b] = blk[idx];
    }
    __syncthreads();
#pragma unroll
    for (int i = 0; i < 4; i++) {
        int it = threadIdx.x + i * 256;
        int b  = it >> 4;
        int q  = it & 15;
        float v0 = sm[(q * 4 + 0) * 65 + b];
        float v1 = sm[(q * 4 + 1) * 65 + b];
        float v2 = sm[(q * 4 + 2) * 65 + b];
        float v3 = sm[(q * 4 + 3) * 65 + b];
        float r0, r1, r2, r3;
        ushort4 hi, lo;
        hi.x = bf16hi_bits(v0, r0); hi.y = bf16hi_bits(v1, r1);
        hi.z = bf16hi_bits(v2, r2); hi.w = bf16hi_bits(v3, r3);
        lo.x = bf16_bits(r0); lo.y = bf16_bits(r1);
        lo.z = bf16_bits(r2); lo.w = bf16_bits(r3);
        uint32_t sw = swz128((uint32_t)(b * 128 + q * 8));
        *(ushort4*)((char*)dh + tbase + sw) = hi;
        *(ushort4*)((char*)dl + tbase + sw) = lo;
    }
}

// =========================================================================
// mma.sync GEMM (unchanged from R6)
// =========================================================================
#define TCB_BYTES 65536
#define TC_SMEM_TOTAL (1024 + 2 * TCB_BYTES)

__global__ __launch_bounds__(256) void k_gemm_mma(
    const __nv_bfloat16* __restrict__ Wh, const __nv_bfloat16* __restrict__ Wl,
    const __nv_bfloat16* __restrict__ Xh, const __nv_bfloat16* __restrict__ Xl,
    const float* __restrict__ bias, float* __restrict__ C,
    int nS, int M, int mode)
{
    extern __shared__ __align__(16) char smem[];
    uint32_t sb = smem_u32(smem);
    int tid  = threadIdx.x;
    int wid  = tid >> 5;
    int lane = tid & 31;
    int mi   = blockIdx.x;
    int m0   = mi * 128;
    int t0   = blockIdx.y * 2;

    int wm = (wid >> 1) * 32;
    int wn = (wid & 1);

    uint32_t pA = (uint32_t)((wm + (lane & 15)) * 128 + (lane >> 4) * 16);
    uint32_t rowB = (uint32_t)((lane & 7) + ((lane >> 4) & 1) * 8);
    uint32_t koffB = (uint32_t)(((lane >> 3) & 1) * 16);

    float acc[2][8][4];
#pragma unroll
    for (int i = 0; i < 2; i++)
#pragma unroll
        for (int n = 0; n < 8; n++)
#pragma unroll
            for (int c = 0; c < 4; c++) acc[i][n][c] = 0.f;

    auto issue_slab = [&](int s, int bi) {
        char* dst = smem + 1024 + bi * TCB_BYTES;
        const char* wh  = (const char*)Wh + ((size_t)mi * nS + s) * 16384;
        const char* wl  = (const char*)Wl + ((size_t)mi * nS + s) * 16384;
        const char* x0h = (const char*)Xh + ((size_t)t0 * nS + s) * 8192;
        const char* x1h = (const char*)Xh + ((size_t)(t0 + 1) * nS + s) * 8192;
        const char* x0l = (const char*)Xl + ((size_t)t0 * nS + s) * 8192;
        const char* x1l = (const char*)Xl + ((size_t)(t0 + 1) * nS + s) * 8192;
#pragma unroll
        for (int i = 0; i < 16; i++) {
            int c   = tid + i * 256;
            int reg = c >> 10;
            int off = (c & 1023) * 16;
            const char* src;
            if      (reg == 0) src = wh + off;
            else if (reg == 1) src = wl + off;
            else if (reg == 2) src = (off < 8192) ? x0h + off : x1h + (off - 8192);
            else               src = (off < 8192) ? x0l + off : x1l + (off - 8192);
            cp_async16(dst + reg * 16384 + off, src);
        }
        cp_commit();
    };

    issue_slab(0, 0);

    for (int s = 0; s < nS; s++) {
        int bi = s & 1;
        if (s + 1 < nS) {
            issue_slab(s + 1, (s + 1) & 1);
            cp_wait<1>();
        } else {
            cp_wait<0>();
        }
        __syncthreads();

        uint32_t bufb = sb + 1024 + (uint32_t)bi * TCB_BYTES;
        uint32_t aH = bufb;
        uint32_t aL = bufb + 16384;
        uint32_t bH = bufb + 32768 + (uint32_t)wn * 8192;
        uint32_t bL = bufb + 49152 + (uint32_t)wn * 8192;

#pragma unroll
        for (int ks = 0; ks < 4; ks++) {
            unsigned ah[2][4], al[2][4];
            ldsm_x4(ah[0], aH + swz128(pA + ks * 32));
            ldsm_x4(ah[1], aH + swz128(pA + 2048 + ks * 32));
            ldsm_x4(al[0], aL + swz128(pA + ks * 32));
            ldsm_x4(al[1], aL + swz128(pA + 2048 + ks * 32));
#pragma unroll
            for (int half = 0; half < 2; half++) {
                unsigned bh2[2][4], bl2[2][4];
#pragma unroll
                for (int np2 = 0; np2 < 2; np2++) {
                    int np = half * 2 + np2;
                    uint32_t pB = (uint32_t)((np * 16 + rowB) * 128) + koffB;
                    ldsm_x4(bh2[np2], bH + swz128(pB + ks * 32));
                    ldsm_x4(bl2[np2], bL + swz128(pB + ks * 32));
                }
#pragma unroll
                for (int np2 = 0; np2 < 2; np2++) {
#pragma unroll
                    for (int e = 0; e < 2; e++) {
                        int nt = half * 4 + np2 * 2 + e;
                        const unsigned* bfh = &bh2[np2][e * 2];
                        const unsigned* bfl = &bl2[np2][e * 2];
#pragma unroll
                        for (int i = 0; i < 2; i++) {
                            mma_bf16(acc[i][nt], ah[i], bfh);
                            mma_bf16(acc[i][nt], ah[i], bfl);
                            mma_bf16(acc[i][nt], al[i], bfh);
                        }
                    }
                }
            }
        }
        __syncthreads();
    }

    int qrow = lane >> 2;
    int qcol = (lane & 3) * 2;

    if (mode == 0) {
        int t = t0 + wn;
#pragma unroll
        for (int i = 0; i < 2; i++) {
            int r0 = wm + i * 16 + qrow;
            int r1 = r0 + 8;
            float bb0 = bias[m0 + r0];
            float bb1 = bias[m0 + r1];
            float* d0 = C + ((size_t)t * M + m0 + r0) * B_;
            float* d1 = C + ((size_t)t * M + m0 + r1) * B_;
#pragma unroll
            for (int nt = 0; nt < 8; nt++) {
                int col = nt * 8 + qcol;
                *(float2*)(d0 + col) = make_float2(acc[i][nt][0] + bb0, acc[i][nt][1] + bb0);
                *(float2*)(d1 + col) = make_float2(acc[i][nt][2] + bb1, acc[i][nt][3] + bb1);
            }
        }
    } else {
        float* stage = (float*)(smem + 1024);
#pragma unroll
        for (int i = 0; i < 2; i++) {
            int r0 = wm + i * 16 + qrow;
            int r1 = r0 + 8;
            float bb0 = bias[m0 + r0];
            float bb1 = bias[m0 + r1];
#pragma unroll
            for (int nt = 0; nt < 8; nt++) {
                int col = wn * 64 + nt * 8 + qcol;
                stage[r0 * 132 + col]     = acc[i][nt][0] + bb0;
                stage[r0 * 132 + col + 1] = acc[i][nt][1] + bb0;
                stage[r1 * 132 + col]     = acc[i][nt][2] + bb1;
                stage[r1 * 132 + col + 1] = acc[i][nt][3] + bb1;
            }
        }
        __syncthreads();
        int n    = tid >> 1;
        int half = tid & 1;
        int tt   = t0 + (n >> 6);
        int b2   = n & 63;
        float* dst = C + ((size_t)b2 * T_ + tt) * M + m0 + half * 64;
#pragma unroll
        for (int q = 0; q < 16; q++) {
            float4 v = make_float4(stage[(half * 64 + q * 4 + 0) * 132 + n],
                                   stage[(half * 64 + q * 4 + 1) * 132 + n],
                                   stage[(half * 64 + q * 4 + 2) * 132 + n],
                                   stage[(half * 64 + q * 4 + 3) * 132 + n]);
            *(float4*)(dst + q * 4) = v;
        }
    }
}

// =========================================================================
// Persistent GRU layer: R6 structure + flag-array barrier.
// 128 CTAs = 4 batch-groups (16 b) x 32 j-subs (16 j).
// Barrier: each CTA st.release's its OWN flag = t+1; warp 0's 32 lanes
// ld.acquire-poll all 32 group flags (one coalesced 128B wavefront).
// =========================================================================
#define WS_STRIDE 520
#define HS_STRIDE 516
#define GRU_SMEM_BYTES ((48 * WS_STRIDE + 16 * HS_STRIDE) * 4)

__global__ __launch_bounds__(256) void k_gru6(
    const float* __restrict__ gates,   // [t][g][b], includes b_ih
    const float* __restrict__ Whh,     // [3H][H]
    const float* __restrict__ bhh,     // [3H]
    float* __restrict__ out)           // [t][h][b]
{
    extern __shared__ float smemf[];
    float* Ws = smemf;
    float* hs = smemf + 48 * WS_STRIDE;

    int tid   = threadIdx.x;
    int w     = tid >> 5;
    int lane  = tid & 31;
    int group = blockIdx.x >> 5;
    int sub   = blockIdx.x & 31;
    int jj    = (w >> 1) * 4 + (lane >> 3);
    int bl    = (w & 1) * 8 + (lane & 7);
    int j0    = sub * 16;
    int bg0   = group * 16;
    int j     = j0 + jj;
    int b     = bg0 + bl;
    unsigned* flags = g_flags + group * 32;

    for (int idx = tid; idx < 48 * 512; idx += 256) {
        int r = idx >> 9;
        int k = idx & 511;
        int gg = r % 3;
        int ww = r / 3;
        Ws[r * WS_STRIDE + k] = Whh[((size_t)(gg * H_ + j0 + ww)) * H_ + k];
    }
    for (int idx = tid; idx < 16 * HS_STRIDE; idx += 256) hs[idx] = 0.f;

    float bhr = bhh[j];
    float bhz = bhh[H_ + j];
    float bhn = bhh[2 * H_ + j];

    const ull2* Wr2 = (const ull2*)(Ws + (jj * 3 + 0) * WS_STRIDE);
    const ull2* Wz2 = (const ull2*)(Ws + (jj * 3 + 1) * WS_STRIDE);
    const ull2* Wn2 = (const ull2*)(Ws + (jj * 3 + 2) * WS_STRIDE);
    const ull2* hrow = (const ull2*)(hs + bl * HS_STRIDE);

    const float* gp = gates + (size_t)j * B_ + b;
    const size_t tstride = (size_t)G_ * B_;
    const size_t goff    = (size_t)H_ * B_;

    float xr = __ldcs(gp);
    float xz = __ldcs(gp + goff);
    float xn = __ldcs(gp + 2 * goff);

    __syncthreads();

    for (int t = 0; t < T_; t++) {
        unsigned long long ar2 = 0ull, az2 = 0ull, an2 = 0ull;
#pragma unroll 8
        for (int i = 0; i < 128; i++) {
            ull2 h2 = hrow[i];
            ull2 wr = Wr2[i];
            ull2 wz = Wz2[i];
            ull2 wn = Wn2[i];
            FMA2(ar2, wr.x, h2.x); FMA2(ar2, wr.y, h2.y);
            FMA2(az2, wz.x, h2.x); FMA2(az2, wz.y, h2.y);
            FMA2(an2, wn.x, h2.x); FMA2(an2, wn.y, h2.y);
        }
        float ar = sum2(ar2);
        float az = sum2(az2);
        float an = sum2(an2);

        float r = 1.f / (1.f + expf(-(xr + ar + bhr)));
        float z = 1.f / (1.f + expf(-(xz + az + bhz)));
        float n = tanhf(xn + r * (an + bhn));
        float hold = hs[bl * HS_STRIDE + j];
        float hnew = (1.f - z) * n + z * hold;

        out[((size_t)t * H_ + j) * B_ + b] = hnew;

        // prefetch next-step gates (independent of h)
        if (t + 1 < T_) {
            const float* gq = gp + (size_t)(t + 1) * tstride;
            xr = __ldcs(gq);
            xz = __ldcs(gq + goff);
            xn = __ldcs(gq + 2 * goff);
        }

        // ---- flag-array barrier over the 32 group CTAs ----
        __syncthreads();        // all h writes of this CTA issued
        if (w == 0) {
            unsigned epoch = (unsigned)(t + 1);
            if (lane == 0) st_release(&flags[sub], epoch);
            unsigned v;
            do {
                v = ld_acquire(&flags[lane]);
            } while (__any_sync(0xffffffffu, (int)(v - epoch) < 0));
        }
        __syncthreads();

        // ---- reload group's h slice: hs[b_local][k] <- out[t][k][bg0+b] ----
        {
            const float* src = out + (size_t)t * H_ * B_;
            int kk0 = tid >> 2;
            int q   = tid & 3;
#pragma unroll
            for (int u = 0; u < 8; u++) {
                int k = kk0 + u * 64;
                float4 v = __ldcg(reinterpret_cast<const float4*>(src + (size_t)k * B_ + bg0) + q);
                int bb = q * 4;
                hs[(bb + 0) * HS_STRIDE + k] = v.x;
                hs[(bb + 1) * HS_STRIDE + k] = v.y;
                hs[(bb + 2) * HS_STRIDE + k] = v.z;
                hs[(bb + 3) * HS_STRIDE + k] = v.w;
            }
        }
        __syncthreads();
    }
}

// =========================================================================
// hidden[l][b][h] = out_l[T-1][h][b]
// =========================================================================
__global__ __launch_bounds__(256) void k_hidden(float* __restrict__ dst) {
    int idx = blockIdx.x * 256 + threadIdx.x;
    int l  = idx >> 15;
    int rem = idx & 32767;
    int bb = rem >> 9;
    int h  = rem & 511;
    const float* src = l ? g_out1 : g_out0;
    dst[idx] = src[((size_t)(T_ - 1) * H_ + h) * B_ + bb];
}

// =========================================================================
extern "C" void kernel_launch(void* const* d_in, const int* in_sizes, int n_in,
                              void* d_out, int out_size) {
    const float* x    = (const float*)d_in[0];
    const float* Wih0 = (const float*)d_in[1];
    const float* Whh0 = (const float*)d_in[2];
    const float* bih0 = (const float*)d_in[3];
    const float* bhh0 = (const float*)d_in[4];
    const float* Wih1 = (const float*)d_in[5];
    const float* Whh1 = (const float*)d_in[6];
    const float* bih1 = (const float*)d_in[7];
    const float* bhh1 = (const float*)d_in[8];
    const float* fcw  = (const float*)d_in[9];
    const float* fcb  = (const float*)d_in[10];
    float* out = (float*)d_out;

    (void)in_sizes; (void)n_in; (void)out_size;

    cudaFuncSetAttribute(k_gru6, cudaFuncAttributeMaxDynamicSharedMemorySize,
                         GRU_SMEM_BYTES);
    cudaFuncSetAttribute(k_gemm_mma, cudaFuncAttributeMaxDynamicSharedMemorySize,
                         TC_SMEM_TOTAL);

    float *p_gates, *p_out0, *p_out1;
    cudaGetSymbolAddress((void**)&p_gates, g_gates);
    cudaGetSymbolAddress((void**)&p_out0,  g_out0);
    cudaGetSymbolAddress((void**)&p_out1,  g_out1);
    __nv_bfloat16 *w0h, *w0l, *w1h, *w1l, *wfh, *wfl, *x0h, *x0l, *x1h, *x1l;
    cudaGetSymbolAddress((void**)&w0h, g_w0h);
    cudaGetSymbolAddress((void**)&w0l, g_w0l);
    cudaGetSymbolAddress((void**)&w1h, g_w1h);
    cudaGetSymbolAddress((void**)&w1l, g_w1l);
    cudaGetSymbolAddress((void**)&wfh, g_wfh);
    cudaGetSymbolAddress((void**)&wfl, g_wfl);
    cudaGetSymbolAddress((void**)&x0h, g_x0h);
    cudaGetSymbolAddress((void**)&x0l, g_x0l);
    cudaGetSymbolAddress((void**)&x1h, g_x1h);
    cudaGetSymbolAddress((void**)&x1l, g_x1l);

    // operand prep
    k_prep_w<<<dim3(12, 4), 256>>>(Wih0, w0h, w0l, I_);
    k_prep_w<<<dim3(12, 8), 256>>>(Wih1, w1h, w1l, H_);
    k_prep_w<<<dim3(2, 8),  256>>>(fcw,  wfh, wfl, H_);
    k_prep_x<<<dim3(1024, 4), 256>>>(x);

    // layer 0
    k_gemm_mma<<<dim3(12, 512), 256, TC_SMEM_TOTAL>>>(w0h, w0l, x0h, x0l, bih0, p_gates, 4, G_, 0);
    k_zeroflags<<<1, 128>>>();
    k_gru6<<<128, 256, GRU_SMEM_BYTES>>>(p_gates, Whh0, bhh0, p_out0);

    // layer 1
    k_prep_h<<<dim3(1024, 8), 256>>>(p_out0, x1h, x1l);
    k_gemm_mma<<<dim3(12, 512), 256, TC_SMEM_TOTAL>>>(w1h, w1l, x1h, x1l, bih1, p_gates, 8, G_, 0);
    k_zeroflags<<<1, 128>>>();
    k_gru6<<<128, 256, GRU_SMEM_BYTES>>>(p_gates, Whh1, bhh1, p_out1);

    // FC
    k_prep_h<<<dim3(1024, 8), 256>>>(p_out1, x1h, x1l);
    k_gemm_mma<<<dim3(2, 512), 256, TC_SMEM_TOTAL>>>(wfh, wfl, x1h, x1l, fcb, out, 8, O_, 1);

    k_hidden<<<256, 256>>>(out + (size_t)B_ * T_ * O_);
}

// round 9
// speedup vs baseline: 1.6584x; 1.5950x over previous
#include <cuda_runtime.h>
#include <cuda_bf16.h>
#include <cstdint>

#define B_ 64
#define T_ 1024
#define I_ 256
#define H_ 512
#define O_ 256
#define G_ 1536   // 3*H

struct __align__(16) ull2 { unsigned long long x, y; };

#define FMA2(acc, av, bv) \
    asm("fma.rn.f32x2 %0, %1, %2, %0;" : "+l"(acc) : "l"(av), "l"(bv))

// ======================= scratch (device globals) =======================
__device__ float g_gates[(size_t)T_ * G_ * B_];   // [t][g][b]
__device__ float g_out0[(size_t)T_ * H_ * B_];    // [t][h][b]
__device__ float g_out1[(size_t)T_ * H_ * B_];    // [t][h][b]
__device__ unsigned g_cnt[8 * 32];                 // per-group barrier counters (padded)
__device__ unsigned g_gen2[8 * 32];                // per-group generations (padded)

// pre-swizzled bf16 operand tiles
__device__ __nv_bfloat16 g_w0h[12 * 4 * 8192], g_w0l[12 * 4 * 8192];
__device__ __nv_bfloat16 g_w1h[12 * 8 * 8192], g_w1l[12 * 8 * 8192];
__device__ __nv_bfloat16 g_wfh[ 2 * 8 * 8192], g_wfl[ 2 * 8 * 8192];
__device__ __nv_bfloat16 g_x0h[(size_t)T_ * 4 * 4096], g_x0l[(size_t)T_ * 4 * 4096];
__device__ __nv_bfloat16 g_x1h[(size_t)T_ * 8 * 4096], g_x1l[(size_t)T_ * 8 * 4096];

// ======================= small helpers =======================
__device__ __forceinline__ void cp_async16(void* smem_dst, const void* gsrc) {
    unsigned s = (unsigned)__cvta_generic_to_shared(smem_dst);
    asm volatile("cp.async.ca.shared.global [%0], [%1], 16;" :: "r"(s), "l"(gsrc));
}
__device__ __forceinline__ void cp_commit() {
    asm volatile("cp.async.commit_group;");
}
template <int N>
__device__ __forceinline__ void cp_wait() {
    asm volatile("cp.async.wait_group %0;" :: "n"(N));
}
__device__ __forceinline__ unsigned atom_add_release(unsigned* p, unsigned v) {
    unsigned old;
    asm volatile("atom.add.release.gpu.global.u32 %0, [%1], %2;"
                 : "=r"(old) : "l"(p), "r"(v) : "memory");
    return old;
}
__device__ __forceinline__ unsigned ld_acquire(const unsigned* p) {
    unsigned v;
    asm volatile("ld.acquire.gpu.global.u32 %0, [%1];" : "=r"(v) : "l"(p) : "memory");
    return v;
}
__device__ __forceinline__ void st_release(unsigned* p, unsigned v) {
    asm volatile("st.release.gpu.global.u32 [%0], %1;" :: "l"(p), "r"(v) : "memory");
}
__device__ __forceinline__ float sum2(unsigned long long v) {
    unsigned lo, hi;
    asm("mov.b64 {%0, %1}, %2;" : "=r"(lo), "=r"(hi) : "l"(v));
    return __uint_as_float(lo) + __uint_as_float(hi);
}
__device__ __forceinline__ uint32_t smem_u32(const void* p) {
    return (uint32_t)__cvta_generic_to_shared(p);
}
__host__ __device__ __forceinline__ uint32_t swz128(uint32_t o) {
    return o ^ ((o >> 3) & 0x70);
}
__device__ __forceinline__ unsigned short bf16hi_bits(float v, float& rem) {
    __nv_bfloat16 b = __float2bfloat16(v);
    rem = v - __bfloat162float(b);
    return *reinterpret_cast<unsigned short*>(&b);
}
__device__ __forceinline__ unsigned short bf16_bits(float v) {
    __nv_bfloat16 b = __float2bfloat16(v);
    return *reinterpret_cast<unsigned short*>(&b);
}

// ---- mma.sync / ldmatrix (base-target PTX) ----
__device__ __forceinline__ void ldsm_x4(unsigned* r, uint32_t addr) {
    asm volatile("ldmatrix.sync.aligned.m8n8.x4.shared.b16 {%0,%1,%2,%3}, [%4];"
        : "=r"(r[0]), "=r"(r[1]), "=r"(r[2]), "=r"(r[3]) : "r"(addr));
}
__device__ __forceinline__ void mma_bf16(float* d, const unsigned* a, const unsigned* b) {
    asm volatile(
        "mma.sync.aligned.m16n8k16.row.col.f32.bf16.bf16.f32 "
        "{%0,%1,%2,%3}, {%4,%5,%6,%7}, {%8,%9}, {%0,%1,%2,%3};"
        : "+f"(d[0]), "+f"(d[1]), "+f"(d[2]), "+f"(d[3])
        : "r"(a[0]), "r"(a[1]), "r"(a[2]), "r"(a[3]), "r"(b[0]), "r"(b[1]));
}

// =========================================================================
// Prep: W [M,K] fp32 -> hi/lo bf16 SW128 tiles [mi][s][128x64]
// =========================================================================
__global__ __launch_bounds__(256) void k_prep_w(
    const float* __restrict__ src, __nv_bfloat16* __restrict__ dh,
    __nv_bfloat16* __restrict__ dl, int K)
{
    int mi = blockIdx.x, s = blockIdx.y, nS = gridDim.y;
    size_t tbase = ((size_t)mi * nS + s) * 16384;
#pragma unroll
    for (int i = 0; i < 8; i++) {
        int it  = threadIdx.x + i * 256;
        int row = it >> 4;
        int q   = it & 15;
        float4 v = *(const float4*)(src + (size_t)(mi * 128 + row) * K + s * 64 + q * 4);
        float r0, r1, r2, r3;
        ushort4 hi, lo;
        hi.x = bf16hi_bits(v.x, r0); hi.y = bf16hi_bits(v.y, r1);
        hi.z = bf16hi_bits(v.z, r2); hi.w = bf16hi_bits(v.w, r3);
        lo.x = bf16_bits(r0); lo.y = bf16_bits(r1);
        lo.z = bf16_bits(r2); lo.w = bf16_bits(r3);
        uint32_t sw = swz128((uint32_t)(row * 128 + q * 8));
        *(ushort4*)((char*)dh + tbase + sw) = hi;
        *(ushort4*)((char*)dl + tbase + sw) = lo;
    }
}

// =========================================================================
// Prep: x[b][t][k] fp32 -> hi/lo bf16 SW128 tiles [t][s][64(b)x64(k)]
// =========================================================================
__global__ __launch_bounds__(256) void k_prep_x(const float* __restrict__ x) {
    int t = blockIdx.x, s = blockIdx.y, nS = gridDim.y;
    size_t tbase = ((size_t)t * nS + s) * 8192;
#pragma unroll
    for (int i = 0; i < 4; i++) {
        int it = threadIdx.x + i * 256;
        int b  = it >> 4;
        int q  = it & 15;
        float4 v = *(const float4*)(x + ((size_t)b * T_ + t) * I_ + s * 64 + q * 4);
        float r0, r1, r2, r3;
        ushort4 hi, lo;
        hi.x = bf16hi_bits(v.x, r0); hi.y = bf16hi_bits(v.y, r1);
        hi.z = bf16hi_bits(v.z, r2); hi.w = bf16hi_bits(v.w, r3);
        lo.x = bf16_bits(r0); lo.y = bf16_bits(r1);
        lo.z = bf16_bits(r2); lo.w = bf16_bits(r3);
        uint32_t sw = swz128((uint32_t)(b * 128 + q * 8));
        *(ushort4*)((char*)g_x0h + tbase + sw) = hi;
        *(ushort4*)((char*)g_x0l + tbase + sw) = lo;
    }
}

// =========================================================================
// Prep: out[t][h][b] fp32 -> hi/lo bf16 SW128 tiles [t][s][64(b)x64(k)]
// =========================================================================
__global__ __launch_bounds__(256) void k_prep_h(
    const float* __restrict__ src, __nv_bfloat16* __restrict__ dh,
    __nv_bfloat16* __restrict__ dl)
{
    __shared__ float sm[64 * 65];
    int t = blockIdx.x, s = blockIdx.y, nS = gridDim.y;
    size_t tbase = ((size_t)t * nS + s) * 8192;
    const float* blk = src + ((size_t)t * H_ + s * 64) * B_;
#pragma unroll
    for (int i = 0; i < 16; i++) {
        int idx = threadIdx.x + i * 256;
        int k = idx >> 6, b = idx & 63;
        sm[k * 65 + b] = blk[idx];
    }
    __syncthreads();
#pragma unroll
    for (int i = 0; i < 4; i++) {
        int it = threadIdx.x + i * 256;
        int b  = it >> 4;
        int q  = it & 15;
        float v0 = sm[(q * 4 + 0) * 65 + b];
        float v1 = sm[(q * 4 + 1) * 65 + b];
        float v2 = sm[(q * 4 + 2) * 65 + b];
        float v3 = sm[(q * 4 + 3) * 65 + b];
        float r0, r1, r2, r3;
        ushort4 hi, lo;
        hi.x = bf16hi_bits(v0, r0); hi.y = bf16hi_bits(v1, r1);
        hi.z = bf16hi_bits(v2, r2); hi.w = bf16hi_bits(v3, r3);
        lo.x = bf16_bits(r0); lo.y = bf16_bits(r1);
        lo.z = bf16_bits(r2); lo.w = bf16_bits(r3);
        uint32_t sw = swz128((uint32_t)(b * 128 + q * 8));
        *(ushort4*)((char*)dh + tbase + sw) = hi;
        *(ushort4*)((char*)dl + tbase + sw) = lo;
    }
}

// =========================================================================
// mma.sync GEMM (unchanged from R6)
// =========================================================================
#define TCB_BYTES 65536
#define TC_SMEM_TOTAL (1024 + 2 * TCB_BYTES)

__global__ __launch_bounds__(256) void k_gemm_mma(
    const __nv_bfloat16* __restrict__ Wh, const __nv_bfloat16* __restrict__ Wl,
    const __nv_bfloat16* __restrict__ Xh, const __nv_bfloat16* __restrict__ Xl,
    const float* __restrict__ bias, float* __restrict__ C,
    int nS, int M, int mode)
{
    extern __shared__ __align__(16) char smem[];
    uint32_t sb = smem_u32(smem);
    int tid  = threadIdx.x;
    int wid  = tid >> 5;
    int lane = tid & 31;
    int mi   = blockIdx.x;
    int m0   = mi * 128;
    int t0   = blockIdx.y * 2;

    int wm = (wid >> 1) * 32;
    int wn = (wid & 1);

    uint32_t pA = (uint32_t)((wm + (lane & 15)) * 128 + (lane >> 4) * 16);
    uint32_t rowB = (uint32_t)((lane & 7) + ((lane >> 4) & 1) * 8);
    uint32_t koffB = (uint32_t)(((lane >> 3) & 1) * 16);

    float acc[2][8][4];
#pragma unroll
    for (int i = 0; i < 2; i++)
#pragma unroll
        for (int n = 0; n < 8; n++)
#pragma unroll
            for (int c = 0; c < 4; c++) acc[i][n][c] = 0.f;

    auto issue_slab = [&](int s, int bi) {
        char* dst = smem + 1024 + bi * TCB_BYTES;
        const char* wh  = (const char*)Wh + ((size_t)mi * nS + s) * 16384;
        const char* wl  = (const char*)Wl + ((size_t)mi * nS + s) * 16384;
        const char* x0h = (const char*)Xh + ((size_t)t0 * nS + s) * 8192;
        const char* x1h = (const char*)Xh + ((size_t)(t0 + 1) * nS + s) * 8192;
        const char* x0l = (const char*)Xl + ((size_t)t0 * nS + s) * 8192;
        const char* x1l = (const char*)Xl + ((size_t)(t0 + 1) * nS + s) * 8192;
#pragma unroll
        for (int i = 0; i < 16; i++) {
            int c   = tid + i * 256;
            int reg = c >> 10;
            int off = (c & 1023) * 16;
            const char* src;
            if      (reg == 0) src = wh + off;
            else if (reg == 1) src = wl + off;
            else if (reg == 2) src = (off < 8192) ? x0h + off : x1h + (off - 8192);
            else               src = (off < 8192) ? x0l + off : x1l + (off - 8192);
            cp_async16(dst + reg * 16384 + off, src);
        }
        cp_commit();
    };

    issue_slab(0, 0);

    for (int s = 0; s < nS; s++) {
        int bi = s & 1;
        if (s + 1 < nS) {
            issue_slab(s + 1, (s + 1) & 1);
            cp_wait<1>();
        } else {
            cp_wait<0>();
        }
        __syncthreads();

        uint32_t bufb = sb + 1024 + (uint32_t)bi * TCB_BYTES;
        uint32_t aH = bufb;
        uint32_t aL = bufb + 16384;
        uint32_t bH = bufb + 32768 + (uint32_t)wn * 8192;
        uint32_t bL = bufb + 49152 + (uint32_t)wn * 8192;

#pragma unroll
        for (int ks = 0; ks < 4; ks++) {
            unsigned ah[2][4], al[2][4];
            ldsm_x4(ah[0], aH + swz128(pA + ks * 32));
            ldsm_x4(ah[1], aH + swz128(pA + 2048 + ks * 32));
            ldsm_x4(al[0], aL + swz128(pA + ks * 32));
            ldsm_x4(al[1], aL + swz128(pA + 2048 + ks * 32));
#pragma unroll
            for (int half = 0; half < 2; half++) {
                unsigned bh2[2][4], bl2[2][4];
#pragma unroll
                for (int np2 = 0; np2 < 2; np2++) {
                    int np = half * 2 + np2;
                    uint32_t pB = (uint32_t)((np * 16 + rowB) * 128) + koffB;
                    ldsm_x4(bh2[np2], bH + swz128(pB + ks * 32));
                    ldsm_x4(bl2[np2], bL + swz128(pB + ks * 32));
                }
#pragma unroll
                for (int np2 = 0; np2 < 2; np2++) {
#pragma unroll
                    for (int e = 0; e < 2; e++) {
                        int nt = half * 4 + np2 * 2 + e;
                        const unsigned* bfh = &bh2[np2][e * 2];
                        const unsigned* bfl = &bl2[np2][e * 2];
#pragma unroll
                        for (int i = 0; i < 2; i++) {
                            mma_bf16(acc[i][nt], ah[i], bfh);
                            mma_bf16(acc[i][nt], ah[i], bfl);
                            mma_bf16(acc[i][nt], al[i], bfh);
                        }
                    }
                }
            }
        }
        __syncthreads();
    }

    int qrow = lane >> 2;
    int qcol = (lane & 3) * 2;

    if (mode == 0) {
        int t = t0 + wn;
#pragma unroll
        for (int i = 0; i < 2; i++) {
            int r0 = wm + i * 16 + qrow;
            int r1 = r0 + 8;
            float bb0 = bias[m0 + r0];
            float bb1 = bias[m0 + r1];
            float* d0 = C + ((size_t)t * M + m0 + r0) * B_;
            float* d1 = C + ((size_t)t * M + m0 + r1) * B_;
#pragma unroll
            for (int nt = 0; nt < 8; nt++) {
                int col = nt * 8 + qcol;
                *(float2*)(d0 + col) = make_float2(acc[i][nt][0] + bb0, acc[i][nt][1] + bb0);
                *(float2*)(d1 + col) = make_float2(acc[i][nt][2] + bb1, acc[i][nt][3] + bb1);
            }
        }
    } else {
        float* stage = (float*)(smem + 1024);
#pragma unroll
        for (int i = 0; i < 2; i++) {
            int r0 = wm + i * 16 + qrow;
            int r1 = r0 + 8;
            float bb0 = bias[m0 + r0];
            float bb1 = bias[m0 + r1];
#pragma unroll
            for (int nt = 0; nt < 8; nt++) {
                int col = wn * 64 + nt * 8 + qcol;
                stage[r0 * 132 + col]     = acc[i][nt][0] + bb0;
                stage[r0 * 132 + col + 1] = acc[i][nt][1] + bb0;
                stage[r1 * 132 + col]     = acc[i][nt][2] + bb1;
                stage[r1 * 132 + col + 1] = acc[i][nt][3] + bb1;
            }
        }
        __syncthreads();
        int n    = tid >> 1;
        int half = tid & 1;
        int tt   = t0 + (n >> 6);
        int b2   = n & 63;
        float* dst = C + ((size_t)b2 * T_ + tt) * M + m0 + half * 64;
#pragma unroll
        for (int q = 0; q < 16; q++) {
            float4 v = make_float4(stage[(half * 64 + q * 4 + 0) * 132 + n],
                                   stage[(half * 64 + q * 4 + 1) * 132 + n],
                                   stage[(half * 64 + q * 4 + 2) * 132 + n],
                                   stage[(half * 64 + q * 4 + 3) * 132 + n]);
            *(float4*)(dst + q * 4) = v;
        }
    }
}

// =========================================================================
// Persistent GRU layer: proven atomic-counter barrier, HALVED groups.
// 128 CTAs = 8 batch-groups (8 b each) x 16 j-subs (32 j each).
// SMEM: W slice 96x520 fp32 (~195KB) + h slice [8 b][516] (~16.5KB).
// Thread map: jj = tid>>3 (0..31), bl = tid&7 (0..7).
// =========================================================================
#define WS_STRIDE 520
#define HS_STRIDE 516
#define GRU7_SMEM_BYTES ((96 * WS_STRIDE + 8 * HS_STRIDE) * 4)

__global__ __launch_bounds__(256) void k_gru7(
    const float* __restrict__ gates,   // [t][g][b], includes b_ih
    const float* __restrict__ Whh,     // [3H][H]
    const float* __restrict__ bhh,     // [3H]
    float* __restrict__ out)           // [t][h][b]
{
    extern __shared__ float smemf[];
    float* Ws = smemf;                     // 96 rows (jj*3+g) x WS_STRIDE
    float* hs = smemf + 96 * WS_STRIDE;    // [8 b][HS_STRIDE]

    int tid   = threadIdx.x;
    int group = blockIdx.x >> 4;    // 0..7 (batch group of 8)
    int sub   = blockIdx.x & 15;    // 0..15 (j partition of 32)
    int jj    = tid >> 3;           // 0..31
    int bl    = tid & 7;            // 0..7
    int j0    = sub * 32;
    int bg0   = group * 8;
    int j     = j0 + jj;
    int b     = bg0 + bl;
    int gidx  = group * 32;         // padded barrier slot

    // Load Whh slice: row (ww*3+g) <- Whh[g*H + j0 + ww]
    for (int idx = tid; idx < 96 * 512; idx += 256) {
        int r = idx >> 9;           // 0..95
        int k = idx & 511;
        int gg = r % 3;
        int ww = r / 3;             // 0..31
        Ws[r * WS_STRIDE + k] = Whh[((size_t)(gg * H_ + j0 + ww)) * H_ + k];
    }
    for (int idx = tid; idx < 8 * HS_STRIDE; idx += 256) hs[idx] = 0.f;

    float bhr = bhh[j];
    float bhz = bhh[H_ + j];
    float bhn = bhh[2 * H_ + j];

    const ull2* Wr2 = (const ull2*)(Ws + (jj * 3 + 0) * WS_STRIDE);
    const ull2* Wz2 = (const ull2*)(Ws + (jj * 3 + 1) * WS_STRIDE);
    const ull2* Wn2 = (const ull2*)(Ws + (jj * 3 + 2) * WS_STRIDE);
    const ull2* hrow = (const ull2*)(hs + bl * HS_STRIDE);

    const float* gp = gates + (size_t)j * B_ + b;
    const size_t tstride = (size_t)G_ * B_;
    const size_t goff    = (size_t)H_ * B_;

    float xr = __ldcs(gp);
    float xz = __ldcs(gp + goff);
    float xn = __ldcs(gp + 2 * goff);

    __syncthreads();

    for (int t = 0; t < T_; t++) {
        unsigned long long ar2 = 0ull, az2 = 0ull, an2 = 0ull;
#pragma unroll 8
        for (int i = 0; i < 128; i++) {
            ull2 h2 = hrow[i];
            ull2 wr = Wr2[i];
            ull2 wz = Wz2[i];
            ull2 wn = Wn2[i];
            FMA2(ar2, wr.x, h2.x); FMA2(ar2, wr.y, h2.y);
            FMA2(az2, wz.x, h2.x); FMA2(az2, wz.y, h2.y);
            FMA2(an2, wn.x, h2.x); FMA2(an2, wn.y, h2.y);
        }
        float ar = sum2(ar2);
        float az = sum2(az2);
        float an = sum2(an2);

        float r = 1.f / (1.f + expf(-(xr + ar + bhr)));
        float z = 1.f / (1.f + expf(-(xz + az + bhz)));
        float n = tanhf(xn + r * (an + bhn));
        float hold = hs[bl * HS_STRIDE + j];
        float hnew = (1.f - z) * n + z * hold;

        out[((size_t)t * H_ + j) * B_ + b] = hnew;

        // prefetch next-step gates (independent of h)
        if (t + 1 < T_) {
            const float* gq = gp + (size_t)(t + 1) * tstride;
            xr = __ldcs(gq);
            xz = __ldcs(gq + goff);
            xn = __ldcs(gq + 2 * goff);
        }

        // ---- per-group release/acquire barrier over 16 CTAs ----
        __syncthreads();
        if (tid == 0) {
            unsigned g = g_gen2[gidx];
            if (atom_add_release(&g_cnt[gidx], 1u) == 15u) {
                g_cnt[gidx] = 0u;
                st_release(&g_gen2[gidx], g + 1u);
            } else {
                while (ld_acquire(&g_gen2[gidx]) == g) { }
            }
        }
        __syncthreads();

        // ---- reload group's h slice: hs[b_local][k] <- out[t][k][bg0+b] ----
        {
            const float* src = out + (size_t)t * H_ * B_;
#pragma unroll
            for (int u = 0; u < 4; u++) {
                int idx = tid + u * 256;          // 0..1023
                int k = idx >> 1;                  // 0..511
                int q = idx & 1;                   // which float4 (4 b)
                float4 v = __ldcg(reinterpret_cast<const float4*>(src + (size_t)k * B_ + bg0) + q);
                int bb = q * 4;
                hs[(bb + 0) * HS_STRIDE + k] = v.x;
                hs[(bb + 1) * HS_STRIDE + k] = v.y;
                hs[(bb + 2) * HS_STRIDE + k] = v.z;
                hs[(bb + 3) * HS_STRIDE + k] = v.w;
            }
        }
        __syncthreads();
    }
}

// =========================================================================
// hidden[l][b][h] = out_l[T-1][h][b]
// =========================================================================
__global__ __launch_bounds__(256) void k_hidden(float* __restrict__ dst) {
    int idx = blockIdx.x * 256 + threadIdx.x;
    int l  = idx >> 15;
    int rem = idx & 32767;
    int bb = rem >> 9;
    int h  = rem & 511;
    const float* src = l ? g_out1 : g_out0;
    dst[idx] = src[((size_t)(T_ - 1) * H_ + h) * B_ + bb];
}

// =========================================================================
extern "C" void kernel_launch(void* const* d_in, const int* in_sizes, int n_in,
                              void* d_out, int out_size) {
    const float* x    = (const float*)d_in[0];
    const float* Wih0 = (const float*)d_in[1];
    const float* Whh0 = (const float*)d_in[2];
    const float* bih0 = (const float*)d_in[3];
    const float* bhh0 = (const float*)d_in[4];
    const float* Wih1 = (const float*)d_in[5];
    const float* Whh1 = (const float*)d_in[6];
    const float* bih1 = (const float*)d_in[7];
    const float* bhh1 = (const float*)d_in[8];
    const float* fcw  = (const float*)d_in[9];
    const float* fcb  = (const float*)d_in[10];
    float* out = (float*)d_out;

    (void)in_sizes; (void)n_in; (void)out_size;

    cudaFuncSetAttribute(k_gru7, cudaFuncAttributeMaxDynamicSharedMemorySize,
                         GRU7_SMEM_BYTES);
    cudaFuncSetAttribute(k_gemm_mma, cudaFuncAttributeMaxDynamicSharedMemorySize,
                         TC_SMEM_TOTAL);

    float *p_gates, *p_out0, *p_out1;
    cudaGetSymbolAddress((void**)&p_gates, g_gates);
    cudaGetSymbolAddress((void**)&p_out0,  g_out0);
    cudaGetSymbolAddress((void**)&p_out1,  g_out1);
    __nv_bfloat16 *w0h, *w0l, *w1h, *w1l, *wfh, *wfl, *x0h, *x0l, *x1h, *x1l;
    cudaGetSymbolAddress((void**)&w0h, g_w0h);
    cudaGetSymbolAddress((void**)&w0l, g_w0l);
    cudaGetSymbolAddress((void**)&w1h, g_w1h);
    cudaGetSymbolAddress((void**)&w1l, g_w1l);
    cudaGetSymbolAddress((void**)&wfh, g_wfh);
    cudaGetSymbolAddress((void**)&wfl, g_wfl);
    cudaGetSymbolAddress((void**)&x0h, g_x0h);
    cudaGetSymbolAddress((void**)&x0l, g_x0l);
    cudaGetSymbolAddress((void**)&x1h, g_x1h);
    cudaGetSymbolAddress((void**)&x1l, g_x1l);

    // operand prep
    k_prep_w<<<dim3(12, 4), 256>>>(Wih0, w0h, w0l, I_);
    k_prep_w<<<dim3(12, 8), 256>>>(Wih1, w1h, w1l, H_);
    k_prep_w<<<dim3(2, 8),  256>>>(fcw,  wfh, wfl, H_);
    k_prep_x<<<dim3(1024, 4), 256>>>(x);

    // layer 0
    k_gemm_mma<<<dim3(12, 512), 256, TC_SMEM_TOTAL>>>(w0h, w0l, x0h, x0l, bih0, p_gates, 4, G_, 0);
    k_gru7<<<128, 256, GRU7_SMEM_BYTES>>>(p_gates, Whh0, bhh0, p_out0);

    // layer 1
    k_prep_h<<<dim3(1024, 8), 256>>>(p_out0, x1h, x1l);
    k_gemm_mma<<<dim3(12, 512), 256, TC_SMEM_TOTAL>>>(w1h, w1l, x1h, x1l, bih1, p_gates, 8, G_, 0);
    k_gru7<<<128, 256, GRU7_SMEM_BYTES>>>(p_gates, Whh1, bhh1, p_out1);

    // FC
    k_prep_h<<<dim3(1024, 8), 256>>>(p_out1, x1h, x1l);
    k_gemm_mma<<<dim3(2, 512), 256, TC_SMEM_TOTAL>>>(wfh, wfl, x1h, x1l, fcb, out, 8, O_, 1);

    k_hidden<<<256, 256>>>(out + (size_t)B_ * T_ * O_);
}

// round 10
// speedup vs baseline: 2.7135x; 1.6362x over previous
#include <cuda_runtime.h>
#include <cuda_bf16.h>
#include <cstdint>

#define B_ 64
#define T_ 1024
#define I_ 256
#define H_ 512
#define O_ 256
#define G_ 1536   // 3*H

// ======================= scratch (device globals) =======================
__device__ float g_gates[(size_t)T_ * G_ * B_];   // [t][g][b]
__device__ float g_out0[(size_t)T_ * H_ * B_];    // [t][h][b]
__device__ float g_out1[(size_t)T_ * H_ * B_];    // [t][h][b]
__device__ unsigned g_cnt[8 * 32];                 // per-group barrier counters (padded)
__device__ unsigned g_gen2[8 * 32];                // per-group generations (padded)
__device__ unsigned short g_hbh[2 * 64 * 512];     // h bf16-hi, parity double buffer, [b][k]
__device__ unsigned short g_hbl[2 * 64 * 512];     // h bf16-lo

// pre-swizzled bf16 operand tiles (GEMM phase)
__device__ __nv_bfloat16 g_w0h[12 * 4 * 8192], g_w0l[12 * 4 * 8192];
__device__ __nv_bfloat16 g_w1h[12 * 8 * 8192], g_w1l[12 * 8 * 8192];
__device__ __nv_bfloat16 g_wfh[ 2 * 8 * 8192], g_wfl[ 2 * 8 * 8192];
__device__ __nv_bfloat16 g_x0h[(size_t)T_ * 4 * 4096], g_x0l[(size_t)T_ * 4 * 4096];
__device__ __nv_bfloat16 g_x1h[(size_t)T_ * 8 * 4096], g_x1l[(size_t)T_ * 8 * 4096];

// ======================= small helpers =======================
__device__ __forceinline__ void cp_async16(void* smem_dst, const void* gsrc) {
    unsigned s = (unsigned)__cvta_generic_to_shared(smem_dst);
    asm volatile("cp.async.ca.shared.global [%0], [%1], 16;" :: "r"(s), "l"(gsrc));
}
__device__ __forceinline__ void cp_commit() {
    asm volatile("cp.async.commit_group;");
}
template <int N>
__device__ __forceinline__ void cp_wait() {
    asm volatile("cp.async.wait_group %0;" :: "n"(N));
}
__device__ __forceinline__ unsigned atom_add_release(unsigned* p, unsigned v) {
    unsigned old;
    asm volatile("atom.add.release.gpu.global.u32 %0, [%1], %2;"
                 : "=r"(old) : "l"(p), "r"(v) : "memory");
    return old;
}
__device__ __forceinline__ unsigned ld_acquire(const unsigned* p) {
    unsigned v;
    asm volatile("ld.acquire.gpu.global.u32 %0, [%1];" : "=r"(v) : "l"(p) : "memory");
    return v;
}
__device__ __forceinline__ void st_release(unsigned* p, unsigned v) {
    asm volatile("st.release.gpu.global.u32 [%0], %1;" :: "l"(p), "r"(v) : "memory");
}
__device__ __forceinline__ uint32_t smem_u32(const void* p) {
    return (uint32_t)__cvta_generic_to_shared(p);
}
__host__ __device__ __forceinline__ uint32_t swz128(uint32_t o) {
    return o ^ ((o >> 3) & 0x70);
}
__device__ __forceinline__ unsigned short bf16hi_bits(float v, float& rem) {
    __nv_bfloat16 b = __float2bfloat16(v);
    rem = v - __bfloat162float(b);
    return *reinterpret_cast<unsigned short*>(&b);
}
__device__ __forceinline__ unsigned short bf16_bits(float v) {
    __nv_bfloat16 b = __float2bfloat16(v);
    return *reinterpret_cast<unsigned short*>(&b);
}

// ---- mma.sync / ldmatrix (base-target PTX) ----
__device__ __forceinline__ void ldsm_x4(unsigned* r, uint32_t addr) {
    asm volatile("ldmatrix.sync.aligned.m8n8.x4.shared.b16 {%0,%1,%2,%3}, [%4];"
        : "=r"(r[0]), "=r"(r[1]), "=r"(r[2]), "=r"(r[3]) : "r"(addr));
}
__device__ __forceinline__ void ldsm_x2(unsigned* r, uint32_t addr) {
    asm volatile("ldmatrix.sync.aligned.m8n8.x2.shared.b16 {%0,%1}, [%2];"
        : "=r"(r[0]), "=r"(r[1]) : "r"(addr));
}
__device__ __forceinline__ void mma_bf16(float* d, const unsigned* a, const unsigned* b) {
    asm volatile(
        "mma.sync.aligned.m16n8k16.row.col.f32.bf16.bf16.f32 "
        "{%0,%1,%2,%3}, {%4,%5,%6,%7}, {%8,%9}, {%0,%1,%2,%3};"
        : "+f"(d[0]), "+f"(d[1]), "+f"(d[2]), "+f"(d[3])
        : "r"(a[0]), "r"(a[1]), "r"(a[2]), "r"(a[3]), "r"(b[0]), "r"(b[1]));
}

// =========================================================================
// Prep: W [M,K] fp32 -> hi/lo bf16 SW128 tiles [mi][s][128x64]
// =========================================================================
__global__ __launch_bounds__(256) void k_prep_w(
    const float* __restrict__ src, __nv_bfloat16* __restrict__ dh,
    __nv_bfloat16* __restrict__ dl, int K)
{
    int mi = blockIdx.x, s = blockIdx.y, nS = gridDim.y;
    size_t tbase = ((size_t)mi * nS + s) * 16384;
#pragma unroll
    for (int i = 0; i < 8; i++) {
        int it  = threadIdx.x + i * 256;
        int row = it >> 4;
        int q   = it & 15;
        float4 v = *(const float4*)(src + (size_t)(mi * 128 + row) * K + s * 64 + q * 4);
        float r0, r1, r2, r3;
        ushort4 hi, lo;
        hi.x = bf16hi_bits(v.x, r0); hi.y = bf16hi_bits(v.y, r1);
        hi.z = bf16hi_bits(v.z, r2); hi.w = bf16hi_bits(v.w, r3);
        lo.x = bf16_bits(r0); lo.y = bf16_bits(r1);
        lo.z = bf16_bits(r2); lo.w = bf16_bits(r3);
        uint32_t sw = swz128((uint32_t)(row * 128 + q * 8));
        *(ushort4*)((char*)dh + tbase + sw) = hi;
        *(ushort4*)((char*)dl + tbase + sw) = lo;
    }
}

// =========================================================================
// Prep: x[b][t][k] fp32 -> hi/lo bf16 SW128 tiles [t][s][64(b)x64(k)]
// =========================================================================
__global__ __launch_bounds__(256) void k_prep_x(const float* __restrict__ x) {
    int t = blockIdx.x, s = blockIdx.y, nS = gridDim.y;
    size_t tbase = ((size_t)t * nS + s) * 8192;
#pragma unroll
    for (int i = 0; i < 4; i++) {
        int it = threadIdx.x + i * 256;
        int b  = it >> 4;
        int q  = it & 15;
        float4 v = *(const float4*)(x + ((size_t)b * T_ + t) * I_ + s * 64 + q * 4);
        float r0, r1, r2, r3;
        ushort4 hi, lo;
        hi.x = bf16hi_bits(v.x, r0); hi.y = bf16hi_bits(v.y, r1);
        hi.z = bf16hi_bits(v.z, r2); hi.w = bf16hi_bits(v.w, r3);
        lo.x = bf16_bits(r0); lo.y = bf16_bits(r1);
        lo.z = bf16_bits(r2); lo.w = bf16_bits(r3);
        uint32_t sw = swz128((uint32_t)(b * 128 + q * 8));
        *(ushort4*)((char*)g_x0h + tbase + sw) = hi;
        *(ushort4*)((char*)g_x0l + tbase + sw) = lo;
    }
}

// =========================================================================
// Prep: out[t][h][b] fp32 -> hi/lo bf16 SW128 tiles [t][s][64(b)x64(k)]
// =========================================================================
__global__ __launch_bounds__(256) void k_prep_h(
    const float* __restrict__ src, __nv_bfloat16* __restrict__ dh,
    __nv_bfloat16* __restrict__ dl)
{
    __shared__ float sm[64 * 65];
    int t = blockIdx.x, s = blockIdx.y, nS = gridDim.y;
    size_t tbase = ((size_t)t * nS + s) * 8192;
    const float* blk = src + ((size_t)t * H_ + s * 64) * B_;
#pragma unroll
    for (int i = 0; i < 16; i++) {
        int idx = threadIdx.x + i * 256;
        int k = idx >> 6, b = idx & 63;
        sm[k * 65 + b] = blk[idx];
    }
    __syncthreads();
#pragma unroll
    for (int i = 0; i < 4; i++) {
        int it = threadIdx.x + i * 256;
        int b  = it >> 4;
        int q  = it & 15;
        float v0 = sm[(q * 4 + 0) * 65 + b];
        float v1 = sm[(q * 4 + 1) * 65 + b];
        float v2 = sm[(q * 4 + 2) * 65 + b];
        float v3 = sm[(q * 4 + 3) * 65 + b];
        float r0, r1, r2, r3;
        ushort4 hi, lo;
        hi.x = bf16hi_bits(v0, r0); hi.y = bf16hi_bits(v1, r1);
        hi.z = bf16hi_bits(v2, r2); hi.w = bf16hi_bits(v3, r3);
        lo.x = bf16_bits(r0); lo.y = bf16_bits(r1);
        lo.z = bf16_bits(r2); lo.w = bf16_bits(r3);
        uint32_t sw = swz128((uint32_t)(b * 128 + q * 8));
        *(ushort4*)((char*)dh + tbase + sw) = hi;
        *(ushort4*)((char*)dl + tbase + sw) = lo;
    }
}

// =========================================================================
// mma.sync GEMM (unchanged, validated)
// =========================================================================
#define TCB_BYTES 65536
#define TC_SMEM_TOTAL (1024 + 2 * TCB_BYTES)

__global__ __launch_bounds__(256) void k_gemm_mma(
    const __nv_bfloat16* __restrict__ Wh, const __nv_bfloat16* __restrict__ Wl,
    const __nv_bfloat16* __restrict__ Xh, const __nv_bfloat16* __restrict__ Xl,
    const float* __restrict__ bias, float* __restrict__ C,
    int nS, int M, int mode)
{
    extern __shared__ __align__(16) char smem[];
    uint32_t sb = smem_u32(smem);
    int tid  = threadIdx.x;
    int wid  = tid >> 5;
    int lane = tid & 31;
    int mi   = blockIdx.x;
    int m0   = mi * 128;
    int t0   = blockIdx.y * 2;

    int wm = (wid >> 1) * 32;
    int wn = (wid & 1);

    uint32_t pA = (uint32_t)((wm + (lane & 15)) * 128 + (lane >> 4) * 16);
    uint32_t rowB = (uint32_t)((lane & 7) + ((lane >> 4) & 1) * 8);
    uint32_t koffB = (uint32_t)(((lane >> 3) & 1) * 16);

    float acc[2][8][4];
#pragma unroll
    for (int i = 0; i < 2; i++)
#pragma unroll
        for (int n = 0; n < 8; n++)
#pragma unroll
            for (int c = 0; c < 4; c++) acc[i][n][c] = 0.f;

    auto issue_slab = [&](int s, int bi) {
        char* dst = smem + 1024 + bi * TCB_BYTES;
        const char* wh  = (const char*)Wh + ((size_t)mi * nS + s) * 16384;
        const char* wl  = (const char*)Wl + ((size_t)mi * nS + s) * 16384;
        const char* x0h = (const char*)Xh + ((size_t)t0 * nS + s) * 8192;
        const char* x1h = (const char*)Xh + ((size_t)(t0 + 1) * nS + s) * 8192;
        const char* x0l = (const char*)Xl + ((size_t)t0 * nS + s) * 8192;
        const char* x1l = (const char*)Xl + ((size_t)(t0 + 1) * nS + s) * 8192;
#pragma unroll
        for (int i = 0; i < 16; i++) {
            int c   = tid + i * 256;
            int reg = c >> 10;
            int off = (c & 1023) * 16;
            const char* src;
            if      (reg == 0) src = wh + off;
            else if (reg == 1) src = wl + off;
            else if (reg == 2) src = (off < 8192) ? x0h + off : x1h + (off - 8192);
            else               src = (off < 8192) ? x0l + off : x1l + (off - 8192);
            cp_async16(dst + reg * 16384 + off, src);
        }
        cp_commit();
    };

    issue_slab(0, 0);

    for (int s = 0; s < nS; s++) {
        int bi = s & 1;
        if (s + 1 < nS) {
            issue_slab(s + 1, (s + 1) & 1);
            cp_wait<1>();
        } else {
            cp_wait<0>();
        }
        __syncthreads();

        uint32_t bufb = sb + 1024 + (uint32_t)bi * TCB_BYTES;
        uint32_t aH = bufb;
        uint32_t aL = bufb + 16384;
        uint32_t bH = bufb + 32768 + (uint32_t)wn * 8192;
        uint32_t bL = bufb + 49152 + (uint32_t)wn * 8192;

#pragma unroll
        for (int ks = 0; ks < 4; ks++) {
            unsigned ah[2][4], al[2][4];
            ldsm_x4(ah[0], aH + swz128(pA + ks * 32));
            ldsm_x4(ah[1], aH + swz128(pA + 2048 + ks * 32));
            ldsm_x4(al[0], aL + swz128(pA + ks * 32));
            ldsm_x4(al[1], aL + swz128(pA + 2048 + ks * 32));
#pragma unroll
            for (int half = 0; half < 2; half++) {
                unsigned bh2[2][4], bl2[2][4];
#pragma unroll
                for (int np2 = 0; np2 < 2; np2++) {
                    int np = half * 2 + np2;
                    uint32_t pB = (uint32_t)((np * 16 + rowB) * 128) + koffB;
                    ldsm_x4(bh2[np2], bH + swz128(pB + ks * 32));
                    ldsm_x4(bl2[np2], bL + swz128(pB + ks * 32));
                }
#pragma unroll
                for (int np2 = 0; np2 < 2; np2++) {
#pragma unroll
                    for (int e = 0; e < 2; e++) {
                        int nt = half * 4 + np2 * 2 + e;
                        const unsigned* bfh = &bh2[np2][e * 2];
                        const unsigned* bfl = &bl2[np2][e * 2];
#pragma unroll
                        for (int i = 0; i < 2; i++) {
                            mma_bf16(acc[i][nt], ah[i], bfh);
                            mma_bf16(acc[i][nt], ah[i], bfl);
                            mma_bf16(acc[i][nt], al[i], bfh);
                        }
                    }
                }
            }
        }
        __syncthreads();
    }

    int qrow = lane >> 2;
    int qcol = (lane & 3) * 2;

    if (mode == 0) {
        int t = t0 + wn;
#pragma unroll
        for (int i = 0; i < 2; i++) {
            int r0 = wm + i * 16 + qrow;
            int r1 = r0 + 8;
            float bb0 = bias[m0 + r0];
            float bb1 = bias[m0 + r1];
            float* d0 = C + ((size_t)t * M + m0 + r0) * B_;
            float* d1 = C + ((size_t)t * M + m0 + r1) * B_;
#pragma unroll
            for (int nt = 0; nt < 8; nt++) {
                int col = nt * 8 + qcol;
                *(float2*)(d0 + col) = make_float2(acc[i][nt][0] + bb0, acc[i][nt][1] + bb0);
                *(float2*)(d1 + col) = make_float2(acc[i][nt][2] + bb1, acc[i][nt][3] + bb1);
            }
        }
    } else {
        float* stage = (float*)(smem + 1024);
#pragma unroll
        for (int i = 0; i < 2; i++) {
            int r0 = wm + i * 16 + qrow;
            int r1 = r0 + 8;
            float bb0 = bias[m0 + r0];
            float bb1 = bias[m0 + r1];
#pragma unroll
            for (int nt = 0; nt < 8; nt++) {
                int col = wn * 64 + nt * 8 + qcol;
                stage[r0 * 132 + col]     = acc[i][nt][0] + bb0;
                stage[r0 * 132 + col + 1] = acc[i][nt][1] + bb0;
                stage[r1 * 132 + col]     = acc[i][nt][2] + bb1;
                stage[r1 * 132 + col + 1] = acc[i][nt][3] + bb1;
            }
        }
        __syncthreads();
        int n    = tid >> 1;
        int half = tid & 1;
        int tt   = t0 + (n >> 6);
        int b2   = n & 63;
        float* dst = C + ((size_t)b2 * T_ + tt) * M + m0 + half * 64;
#pragma unroll
        for (int q = 0; q < 16; q++) {
            float4 v = make_float4(stage[(half * 64 + q * 4 + 0) * 132 + n],
                                   stage[(half * 64 + q * 4 + 1) * 132 + n],
                                   stage[(half * 64 + q * 4 + 2) * 132 + n],
                                   stage[(half * 64 + q * 4 + 3) * 132 + n]);
            *(float4*)(dst + q * 4) = v;
        }
    }
}

// =========================================================================
// Persistent GRU layer with TENSOR-CORE recurrent matvec (bf16x3).
// 128 CTAs = 8 batch-groups (8 b) x 16 j-subs (32 j = 96 gate-rows).
// SMEM: Wsh/Wsl bf16 [96][520] (stride 1040B), hh/hl bf16 [8][520],
//       hg stage fp32 [96][12].  h exchanged via gmem bf16 hi/lo [par][b][k].
// Warps 0-5: one m16 tile each, K=512 (32 x m16n8k16 x 3 passes).
// =========================================================================
#define OFF_WL 99840
#define OFF_HH 199680
#define OFF_HL 208000
#define OFF_HG 216640
#define GRU8_SMEM_BYTES 221248

__global__ __launch_bounds__(256) void k_gru8(
    const float* __restrict__ gates,   // [t][g][b], includes b_ih
    const float* __restrict__ Whh,     // [3H][H]
    const float* __restrict__ bhh,     // [3H]
    float* __restrict__ out,           // [t][h][b]
    unsigned short* __restrict__ hbh,  // [2][64][512] bf16-hi bits
    unsigned short* __restrict__ hbl)  // [2][64][512] bf16-lo bits
{
    extern __shared__ __align__(16) char smem[];
    uint32_t sb = smem_u32(smem);

    int tid   = threadIdx.x;
    int w     = tid >> 5;
    int lane  = tid & 31;
    int group = blockIdx.x >> 4;    // 0..7
    int sub   = blockIdx.x & 15;    // 0..15
    int jj    = tid >> 3;           // 0..31
    int bl    = tid & 7;            // 0..7
    int j0    = sub * 32;
    int bg0   = group * 8;
    int j     = j0 + jj;
    int b     = bg0 + bl;
    int gidx  = group * 32;

    // ---- init: Whh slice -> bf16 hi/lo smem, row = jj*3+gate ----
    for (int idx = tid; idx < 96 * 512; idx += 256) {
        int r = idx >> 9;           // 0..95
        int k = idx & 511;
        int gg = r % 3;
        int ww = r / 3;
        float v = Whh[((size_t)(gg * H_ + j0 + ww)) * H_ + k];
        float rem;
        unsigned short hi = bf16hi_bits(v, rem);
        unsigned short lo = bf16_bits(rem);
        *(unsigned short*)(smem + r * 1040 + k * 2)          = hi;
        *(unsigned short*)(smem + OFF_WL + r * 1040 + k * 2) = lo;
    }
    // zero h smem (hh + hl)
    for (int idx = tid; idx < (2 * 8320) / 4; idx += 256)
        *(uint32_t*)(smem + OFF_HH + idx * 4) = 0u;

    float bhr = bhh[j];
    float bhz = bhh[H_ + j];
    float bhn = bhh[2 * H_ + j];
    float hold = 0.f;

    const float* gp = gates + (size_t)j * B_ + b;
    const size_t tstride = (size_t)G_ * B_;
    const size_t goff    = (size_t)H_ * B_;
    float xr = __ldcs(gp);
    float xz = __ldcs(gp + goff);
    float xn = __ldcs(gp + 2 * goff);

    // ldmatrix address patterns (byte offsets, k-chunk added in loop)
    uint32_t paH = sb + (uint32_t)((w * 16 + (lane & 15)) * 1040 + (lane >> 4) * 16);
    uint32_t paL = paH + OFF_WL;
    uint32_t pbH = sb + OFF_HH + (uint32_t)((lane & 7) * 1040 + ((lane >> 3) & 1) * 16);
    uint32_t pbL = pbH + (OFF_HL - OFF_HH);
    float* hg = (float*)(smem + OFF_HG);

    __syncthreads();

    for (int t = 0; t < T_; t++) {
        // ---- tensor-core hg = Ws @ h (warps 0-5) ----
        if (w < 6) {
            float acc[4] = {0.f, 0.f, 0.f, 0.f};
#pragma unroll
            for (int ks = 0; ks < 32; ks++) {
                uint32_t ko = (uint32_t)ks * 32;
                unsigned ah[4], al[4], bh2[2], bl2[2];
                ldsm_x4(ah, paH + ko);
                ldsm_x4(al, paL + ko);
                ldsm_x2(bh2, pbH + ko);
                ldsm_x2(bl2, pbL + ko);
                mma_bf16(acc, ah, bh2);
                mma_bf16(acc, ah, bl2);
                mma_bf16(acc, al, bh2);
            }
            int r0 = w * 16 + (lane >> 2);
            *(float2*)&hg[r0 * 12 + (lane & 3) * 2]       = make_float2(acc[0], acc[1]);
            *(float2*)&hg[(r0 + 8) * 12 + (lane & 3) * 2] = make_float2(acc[2], acc[3]);
        }
        __syncthreads();

        // ---- gate math (all 256 threads, one (j,b) each) ----
        float ar = hg[(jj * 3 + 0) * 12 + bl];
        float az = hg[(jj * 3 + 1) * 12 + bl];
        float an = hg[(jj * 3 + 2) * 12 + bl];

        float r = 1.f / (1.f + expf(-(xr + ar + bhr)));
        float z = 1.f / (1.f + expf(-(xz + az + bhz)));
        float n = tanhf(xn + r * (an + bhn));
        float hnew = (1.f - z) * n + z * hold;
        hold = hnew;

        out[((size_t)t * H_ + j) * B_ + b] = hnew;
        int par = t & 1;
        {
            float rem;
            unsigned short hi = bf16hi_bits(hnew, rem);
            unsigned short lo = bf16_bits(rem);
            hbh[par * 32768 + b * 512 + j] = hi;
            hbl[par * 32768 + b * 512 + j] = lo;
        }

        // prefetch next-step gates (independent of h)
        if (t + 1 < T_) {
            const float* gq = gp + (size_t)(t + 1) * tstride;
            xr = __ldcs(gq);
            xz = __ldcs(gq + goff);
            xn = __ldcs(gq + 2 * goff);
        }

        // ---- per-group release/acquire barrier over 16 CTAs ----
        __syncthreads();
        if (tid == 0) {
            unsigned g = g_gen2[gidx];
            if (atom_add_release(&g_cnt[gidx], 1u) == 15u) {
                g_cnt[gidx] = 0u;
                st_release(&g_gen2[gidx], g + 1u);
            } else {
                while (ld_acquire(&g_gen2[gidx]) == g) { }
            }
        }
        __syncthreads();

        // ---- reload h bf16 hi/lo, verbatim coalesced (no transpose) ----
        {
            int row  = tid >> 5;            // 0..7 (local b)
            int colb = lane * 32;           // byte offset in 1024B row
            const char* srch = (const char*)(hbh + par * 32768 + (bg0 + row) * 512) + colb;
            const char* srcl = (const char*)(hbl + par * 32768 + (bg0 + row) * 512) + colb;
            float4 v0 = __ldcg((const float4*)srch);
            float4 v1 = __ldcg((const float4*)(srch + 16));
            float4 u0 = __ldcg((const float4*)srcl);
            float4 u1 = __ldcg((const float4*)(srcl + 16));
            *(float4*)(smem + OFF_HH + row * 1040 + colb)      = v0;
            *(float4*)(smem + OFF_HH + row * 1040 + colb + 16) = v1;
            *(float4*)(smem + OFF_HL + row * 1040 + colb)      = u0;
            *(float4*)(smem + OFF_HL + row * 1040 + colb + 16) = u1;
        }
        __syncthreads();
    }
}

// =========================================================================
// hidden[l][b][h] = out_l[T-1][h][b]
// =========================================================================
__global__ __launch_bounds__(256) void k_hidden(float* __restrict__ dst) {
    int idx = blockIdx.x * 256 + threadIdx.x;
    int l  = idx >> 15;
    int rem = idx & 32767;
    int bb = rem >> 9;
    int h  = rem & 511;
    const float* src = l ? g_out1 : g_out0;
    dst[idx] = src[((size_t)(T_ - 1) * H_ + h) * B_ + bb];
}

// =========================================================================
extern "C" void kernel_launch(void* const* d_in, const int* in_sizes, int n_in,
                              void* d_out, int out_size) {
    const float* x    = (const float*)d_in[0];
    const float* Wih0 = (const float*)d_in[1];
    const float* Whh0 = (const float*)d_in[2];
    const float* bih0 = (const float*)d_in[3];
    const float* bhh0 = (const float*)d_in[4];
    const float* Wih1 = (const float*)d_in[5];
    const float* Whh1 = (const float*)d_in[6];
    const float* bih1 = (const float*)d_in[7];
    const float* bhh1 = (const float*)d_in[8];
    const float* fcw  = (const float*)d_in[9];
    const float* fcb  = (const float*)d_in[10];
    float* out = (float*)d_out;

    (void)in_sizes; (void)n_in; (void)out_size;

    cudaFuncSetAttribute(k_gru8, cudaFuncAttributeMaxDynamicSharedMemorySize,
                         GRU8_SMEM_BYTES);
    cudaFuncSetAttribute(k_gemm_mma, cudaFuncAttributeMaxDynamicSharedMemorySize,
                         TC_SMEM_TOTAL);

    float *p_gates, *p_out0, *p_out1;
    cudaGetSymbolAddress((void**)&p_gates, g_gates);
    cudaGetSymbolAddress((void**)&p_out0,  g_out0);
    cudaGetSymbolAddress((void**)&p_out1,  g_out1);
    unsigned short *hbh, *hbl;
    cudaGetSymbolAddress((void**)&hbh, g_hbh);
    cudaGetSymbolAddress((void**)&hbl, g_hbl);
    __nv_bfloat16 *w0h, *w0l, *w1h, *w1l, *wfh, *wfl, *x0h, *x0l, *x1h, *x1l;
    cudaGetSymbolAddress((void**)&w0h, g_w0h);
    cudaGetSymbolAddress((void**)&w0l, g_w0l);
    cudaGetSymbolAddress((void**)&w1h, g_w1h);
    cudaGetSymbolAddress((void**)&w1l, g_w1l);
    cudaGetSymbolAddress((void**)&wfh, g_wfh);
    cudaGetSymbolAddress((void**)&wfl, g_wfl);
    cudaGetSymbolAddress((void**)&x0h, g_x0h);
    cudaGetSymbolAddress((void**)&x0l, g_x0l);
    cudaGetSymbolAddress((void**)&x1h, g_x1h);
    cudaGetSymbolAddress((void**)&x1l, g_x1l);

    // operand prep
    k_prep_w<<<dim3(12, 4), 256>>>(Wih0, w0h, w0l, I_);
    k_prep_w<<<dim3(12, 8), 256>>>(Wih1, w1h, w1l, H_);
    k_prep_w<<<dim3(2, 8),  256>>>(fcw,  wfh, wfl, H_);
    k_prep_x<<<dim3(1024, 4), 256>>>(x);

    // layer 0
    k_gemm_mma<<<dim3(12, 512), 256, TC_SMEM_TOTAL>>>(w0h, w0l, x0h, x0l, bih0, p_gates, 4, G_, 0);
    k_gru8<<<128, 256, GRU8_SMEM_BYTES>>>(p_gates, Whh0, bhh0, p_out0, hbh, hbl);

    // layer 1
    k_prep_h<<<dim3(1024, 8), 256>>>(p_out0, x1h, x1l);
    k_gemm_mma<<<dim3(12, 512), 256, TC_SMEM_TOTAL>>>(w1h, w1l, x1h, x1l, bih1, p_gates, 8, G_, 0);
    k_gru8<<<128, 256, GRU8_SMEM_BYTES>>>(p_gates, Whh1, bhh1, p_out1, hbh, hbl);

    // FC
    k_prep_h<<<dim3(1024, 8), 256>>>(p_out1, x1h, x1l);
    k_gemm_mma<<<dim3(2, 512), 256, TC_SMEM_TOTAL>>>(wfh, wfl, x1h, x1l, fcb, out, 8, O_, 1);

    k_hidden<<<256, 256>>>(out + (size_t)B_ * T_ * O_);
}